// round 2
// baseline (speedup 1.0000x reference)
#include <cuda_runtime.h>
#include <math.h>

#define L_SEQ   2048
#define D_IN    1024
#define N_ST    16
#define BATCH   2
#define NTOK    (BATCH * L_SEQ)      // 4096
#define NCHUNK  64
#define CLEN    32                   // L_SEQ / NCHUNK
#define LOG2E   1.4426950408889634f

typedef unsigned long long ull;

// ------------------------------- scratch ----------------------------------
__device__ float g_delta[NTOK * D_IN];                     // (tok, d)
__device__ float g_bc   [NTOK * 32];                       // (tok, n)  n<16:B, n>=16:C
__device__ float g_sd   [BATCH * D_IN * NCHUNK];           // sum of delta per chunk
__device__ float g_hloc [BATCH * D_IN * NCHUNK * N_ST];    // local end state per chunk
__device__ float g_hin  [BATCH * D_IN * NCHUNK * N_ST];    // carry-in per chunk

__device__ __forceinline__ float ex2f(float x) {
    float r; asm("ex2.approx.ftz.f32 %0, %1;" : "=f"(r) : "f"(x)); return r;
}
__device__ __forceinline__ float softplusf(float z) {
    return fmaxf(z, 0.0f) + log1pf(__expf(-fabsf(z)));
}
__device__ __forceinline__ ull packf2(float lo, float hi) {
    ull d; asm("mov.b64 %0, {%1, %2};" : "=l"(d) : "r"(__float_as_uint(lo)), "r"(__float_as_uint(hi)));
    return d;
}
__device__ __forceinline__ void unpackf2(float& lo, float& hi, ull v) {
    unsigned a, b; asm("mov.b64 {%0, %1}, %2;" : "=r"(a), "=r"(b) : "l"(v));
    lo = __uint_as_float(a); hi = __uint_as_float(b);
}
__device__ __forceinline__ ull fma2(ull a, ull b, ull c) {
    ull d; asm("fma.rn.f32x2 %0, %1, %2, %3;" : "=l"(d) : "l"(a), "l"(b), "l"(c));
    return d;
}
__device__ __forceinline__ ull mul2(ull a, ull b) {
    ull d; asm("mul.rn.f32x2 %0, %1, %2;" : "=l"(d) : "l"(a), "l"(b));
    return d;
}
__device__ __forceinline__ ull add2(ull a, ull b) {
    ull d; asm("add.rn.f32x2 %0, %1, %2;" : "=l"(d) : "l"(a), "l"(b));
    return d;
}

// ------------------------- K1: projections + delta -------------------------
// 128 blocks x 256 threads, 32 tokens per block.
__global__ __launch_bounds__(256) void k1_proj(
    const float* __restrict__ x,      // (B,L,D)
    const float* __restrict__ w1,     // (64,1024)
    const float* __restrict__ dtw,    // (1024,32)
    const float* __restrict__ bias,   // (1024)
    const float* __restrict__ gs,     // (B,L)
    const float* __restrict__ gcw,    // (16)
    const float* __restrict__ gcb,    // (16)
    const float* __restrict__ gCw)    // scalar
{
    __shared__ __align__(16) union {
        struct { float  x[64][34];  float2 w2[64][66]; } s1;   // k-major tiles
        struct { float  xd[32][36]; float  dw[128][36]; } s2;
    } sm;

    const int tid = threadIdx.x;
    const int tokbase = blockIdx.x * 32;

    const int kk = tid & 63, qq = tid >> 6;       // loader coords
    const int ct = tid & 15, tt = tid >> 4;       // compute coords
    const int c0 = ct * 4, t0 = tt * 2;

    // ---- stage 1: x_dbl = x @ W1^T, packed over token pairs ----
    ull acc2[4] = {0ull, 0ull, 0ull, 0ull};

    for (int kt = 0; kt < 16; kt++) {
        const int k0 = kt * 64;
#pragma unroll
        for (int r = 0; r < 8; r++) {
            int t = qq + r * 4;
            sm.s1.x[kk][t] = x[(size_t)(tokbase + t) * D_IN + k0 + kk];
        }
#pragma unroll
        for (int r = 0; r < 16; r++) {
            int c = qq + r * 4;
            float wv = w1[(size_t)c * D_IN + k0 + kk];
            sm.s1.w2[kk][c] = make_float2(wv, wv);
        }
        __syncthreads();
#pragma unroll 8
        for (int k2 = 0; k2 < 64; k2++) {
            ull xv = *(const ull*)&sm.s1.x[k2][t0];                      // (x_t0, x_t0+1)
            ulonglong2 wA = *(const ulonglong2*)&sm.s1.w2[k2][c0];       // (w_c0,w_c0),(w_c1,w_c1)
            ulonglong2 wB = *(const ulonglong2*)&sm.s1.w2[k2][c0 + 2];
            acc2[0] = fma2(wA.x, xv, acc2[0]);
            acc2[1] = fma2(wA.y, xv, acc2[1]);
            acc2[2] = fma2(wB.x, xv, acc2[2]);
            acc2[3] = fma2(wB.y, xv, acc2[3]);
        }
        __syncthreads();
    }

    // ---- writeback: c<32 -> smem x_dbl; c>=32 -> B / corrected C to gmem ----
    {
        const float gCwv = gCw[0];
#pragma unroll
        for (int i = 0; i < 4; i++) {
            float lo, hi; unpackf2(lo, hi, acc2[i]);
            int c = c0 + i;
            if (c < 32) {
                sm.s2.xd[t0][c]     = lo;
                sm.s2.xd[t0 + 1][c] = hi;
            } else {
                int n = c - 32;
#pragma unroll
                for (int j = 0; j < 2; j++) {
                    int tok = tokbase + t0 + j;
                    int b = tok >> 11, l = tok & 2047;
                    float v = (j == 0) ? lo : hi;
                    if (n >= 16) {
                        int m = n - 16;
                        float ge = gs[b * 2048 + m * 128 + (l >> 4)] * gcw[l & 15] + gcb[l & 15];
                        v += gCwv * ge;
                    }
                    g_bc[(size_t)tok * 32 + n] = v;
                }
            }
        }
    }

    // ---- stage 2: delta = softplus(x_dbl @ dtW^T + bias), packed over r-pairs ----
    const int dlane = tid & 127, th = tid >> 7;
    for (int db = 0; db < 8; db++) {
        __syncthreads();
#pragma unroll
        for (int i = 0; i < 16; i++) {
            int idx = tid + i * 256;                 // 0..4095 = 128 d * 32 r
            sm.s2.dw[idx >> 5][idx & 31] =
                dtw[(size_t)(db * 128 + (idx >> 5)) * 32 + (idx & 31)];
        }
        __syncthreads();

        ull w2r[16];
        const ulonglong2* wrow = (const ulonglong2*)&sm.s2.dw[dlane][0];
#pragma unroll
        for (int k = 0; k < 8; k++) { ulonglong2 q = wrow[k]; w2r[2*k] = q.x; w2r[2*k+1] = q.y; }
        const int d = db * 128 + dlane;
        const float bz = bias[d];

        for (int t = th * 16; t < th * 16 + 16; t++) {
            const ulonglong2* xrow = (const ulonglong2*)&sm.s2.xd[t][0];
            ull a2 = 0ull, b2 = 0ull;
#pragma unroll
            for (int k = 0; k < 8; k++) {
                ulonglong2 q = xrow[k];
                a2 = fma2(w2r[2*k],     q.x, a2);
                b2 = fma2(w2r[2*k + 1], q.y, b2);
            }
            float lo, hi; unpackf2(lo, hi, add2(a2, b2));
            g_delta[(size_t)(tokbase + t) * D_IN + d] = softplusf(lo + hi + bz);
        }
    }
}

// --------------------- K2: scan phase 1 (chunk summaries) ------------------
// grid 1024 = B(2) * dgroups(8) * chunks(64); 128 threads = 128 d-channels.
__global__ __launch_bounds__(128) void k2_phase1(
    const float* __restrict__ x, const float* __restrict__ alogs)
{
    __shared__ __align__(16) float sB[CLEN][16];
    const int tid = threadIdx.x;
    const int bid = blockIdx.x;
    const int ch = bid & (NCHUNK - 1);
    const int dg = (bid >> 6) & 7;
    const int b  = bid >> 9;
    const int d  = dg * 128 + tid;
    const int l0 = ch * CLEN;

    {   // 32 rows x 4 float4 = 128 loads, one per thread
        int s = tid >> 2, q = tid & 3;
        ((float4*)&sB[s][0])[q] = *(const float4*)&g_bc[(size_t)(b * 2048 + l0 + s) * 32 + q * 4];
    }
    __syncthreads();

    float cn[16];
#pragma unroll
    for (int n = 0; n < 16; n++)
        cn[n] = -__expf(alogs[(size_t)d * 16 + n]) * LOG2E;
    bool fast = true;
#pragma unroll
    for (int n = 1; n < 16; n++) {
        float want = (float)(n + 1) * cn[0];
        fast = fast && (fabsf(cn[n] - want) <= 1e-4f * fabsf(want));
    }

    float sd = 0.f;
    const float* dlt = &g_delta[(size_t)(b * 2048 + l0) * D_IN + d];
    const float* xp  = &x[(size_t)(b * 2048 + l0) * D_IN + d];
    const size_t base = (size_t)(b * 1024 + d) * NCHUNK + ch;

    if (fast) {
        const float c0 = cn[0];
        ull h2[8];
#pragma unroll
        for (int k = 0; k < 8; k++) h2[k] = 0ull;
#pragma unroll 2
        for (int s = 0; s < CLEN; s++) {
            float dv = dlt[(size_t)s * D_IN];
            float xv = xp[(size_t)s * D_IN];
            sd += dv;
            float e  = ex2f(dv * c0);
            float e2 = e * e;
            float u  = dv * xv;
            ull uu = packf2(u, u);
            ull dd = packf2(e2, e2);
            ull pp = packf2(e, e2);
            const ulonglong2* B2 = (const ulonglong2*)&sB[s][0];
            ulonglong2 b0 = B2[0], b1 = B2[1], b2v = B2[2], b3 = B2[3];
            h2[0] = fma2(pp, h2[0], mul2(uu, b0.x)); pp = mul2(pp, dd);
            h2[1] = fma2(pp, h2[1], mul2(uu, b0.y)); pp = mul2(pp, dd);
            h2[2] = fma2(pp, h2[2], mul2(uu, b1.x)); pp = mul2(pp, dd);
            h2[3] = fma2(pp, h2[3], mul2(uu, b1.y)); pp = mul2(pp, dd);
            h2[4] = fma2(pp, h2[4], mul2(uu, b2v.x)); pp = mul2(pp, dd);
            h2[5] = fma2(pp, h2[5], mul2(uu, b2v.y)); pp = mul2(pp, dd);
            h2[6] = fma2(pp, h2[6], mul2(uu, b3.x)); pp = mul2(pp, dd);
            h2[7] = fma2(pp, h2[7], mul2(uu, b3.y));
        }
        g_sd[base] = sd;
#pragma unroll
        for (int k = 0; k < 8; k++) *(ull*)&g_hloc[base * 16 + 2 * k] = h2[k];
    } else {
        float h[16];
#pragma unroll
        for (int n = 0; n < 16; n++) h[n] = 0.f;
        for (int s = 0; s < CLEN; s++) {
            float dv = dlt[(size_t)s * D_IN];
            float xv = xp[(size_t)s * D_IN];
            sd += dv;
            float u = dv * xv;
#pragma unroll
            for (int n = 0; n < 16; n++) {
                float a = ex2f(dv * cn[n]);
                h[n] = a * h[n] + u * sB[s][n];
            }
        }
        g_sd[base] = sd;
#pragma unroll
        for (int n = 0; n < 16; n++) g_hloc[base * 16 + n] = h[n];
    }
}

// ----------------------- K3: combine chunk carries -------------------------
__global__ __launch_bounds__(256) void k3_combine(const float* __restrict__ alogs)
{
    const int tid = blockIdx.x * 256 + threadIdx.x;      // 0..32767
    const int n = tid & 15;
    const int bd = tid >> 4;                             // b*1024 + d
    const int d = bd & 1023;
    const float cnf = -__expf(alogs[(size_t)d * 16 + n]) * LOG2E;

    const size_t base = (size_t)bd * NCHUNK;
    float H = 0.f;
    float sd_n = g_sd[base];
    float hl_n = g_hloc[base * 16 + n];
#pragma unroll 4
    for (int c = 0; c < NCHUNK; c++) {
        float sdv = sd_n, hl = hl_n;
        if (c + 1 < NCHUNK) {
            sd_n = g_sd[base + c + 1];
            hl_n = g_hloc[(base + c + 1) * 16 + n];
        }
        g_hin[(base + c) * 16 + n] = H;
        H = ex2f(sdv * cnf) * H + hl;
    }
}

// ----------------------- K4: scan phase 3 (emit y) --------------------------
__global__ __launch_bounds__(128) void k4_phase3(
    const float* __restrict__ x, const float* __restrict__ alogs,
    const float* __restrict__ Ds, float* __restrict__ y)
{
    __shared__ __align__(16) float sB[CLEN][16];
    __shared__ __align__(16) float sC[CLEN][16];
    const int tid = threadIdx.x;
    const int bid = blockIdx.x;
    const int ch = bid & (NCHUNK - 1);
    const int dg = (bid >> 6) & 7;
    const int b  = bid >> 9;
    const int d  = dg * 128 + tid;
    const int l0 = ch * CLEN;

#pragma unroll
    for (int i = 0; i < 2; i++) {
        int idx = tid + i * 128;                 // 0..255: 32 rows x 8 float4
        int s = idx >> 3, q = idx & 7;
        float4 v = *(const float4*)&g_bc[(size_t)(b * 2048 + l0 + s) * 32 + q * 4];
        if (q < 4) ((float4*)&sB[s][0])[q] = v;
        else       ((float4*)&sC[s][0])[q - 4] = v;
    }
    __syncthreads();

    float cn[16];
#pragma unroll
    for (int n = 0; n < 16; n++)
        cn[n] = -__expf(alogs[(size_t)d * 16 + n]) * LOG2E;
    bool fast = true;
#pragma unroll
    for (int n = 1; n < 16; n++) {
        float want = (float)(n + 1) * cn[0];
        fast = fast && (fabsf(cn[n] - want) <= 1e-4f * fabsf(want));
    }

    const size_t base = (size_t)(b * 1024 + d) * NCHUNK + ch;
    const float dsv = Ds[d];
    const float* dlt = &g_delta[(size_t)(b * 2048 + l0) * D_IN + d];
    const float* xp  = &x[(size_t)(b * 2048 + l0) * D_IN + d];
    float* yp        = &y[(size_t)(b * 2048 + l0) * D_IN + d];

    if (fast) {
        const float c0 = cn[0];
        ull h2[8];
#pragma unroll
        for (int k = 0; k < 8; k++) h2[k] = *(const ull*)&g_hin[base * 16 + 2 * k];
#pragma unroll 2
        for (int s = 0; s < CLEN; s++) {
            float dv = dlt[(size_t)s * D_IN];
            float xv = xp[(size_t)s * D_IN];
            float e  = ex2f(dv * c0);
            float e2 = e * e;
            float u  = dv * xv;
            ull uu = packf2(u, u);
            ull dd = packf2(e2, e2);
            ull pp = packf2(e, e2);
            const ulonglong2* B2 = (const ulonglong2*)&sB[s][0];
            const ulonglong2* C2 = (const ulonglong2*)&sC[s][0];
            ulonglong2 b0 = B2[0], b1 = B2[1], b2v = B2[2], b3 = B2[3];
            ulonglong2 cc0 = C2[0], cc1 = C2[1], cc2 = C2[2], cc3 = C2[3];
            ull y2a, y2b;
            h2[0] = fma2(pp, h2[0], mul2(uu, b0.x)); pp = mul2(pp, dd);
            y2a = mul2(h2[0], cc0.x);
            h2[1] = fma2(pp, h2[1], mul2(uu, b0.y)); pp = mul2(pp, dd);
            y2b = mul2(h2[1], cc0.y);
            h2[2] = fma2(pp, h2[2], mul2(uu, b1.x)); pp = mul2(pp, dd);
            y2a = fma2(h2[2], cc1.x, y2a);
            h2[3] = fma2(pp, h2[3], mul2(uu, b1.y)); pp = mul2(pp, dd);
            y2b = fma2(h2[3], cc1.y, y2b);
            h2[4] = fma2(pp, h2[4], mul2(uu, b2v.x)); pp = mul2(pp, dd);
            y2a = fma2(h2[4], cc2.x, y2a);
            h2[5] = fma2(pp, h2[5], mul2(uu, b2v.y)); pp = mul2(pp, dd);
            y2b = fma2(h2[5], cc2.y, y2b);
            h2[6] = fma2(pp, h2[6], mul2(uu, b3.x)); pp = mul2(pp, dd);
            y2a = fma2(h2[6], cc3.x, y2a);
            h2[7] = fma2(pp, h2[7], mul2(uu, b3.y));
            y2b = fma2(h2[7], cc3.y, y2b);
            float ylo, yhi; unpackf2(ylo, yhi, add2(y2a, y2b));
            yp[(size_t)s * D_IN] = ylo + yhi + xv * dsv;
        }
    } else {
        float h[16];
#pragma unroll
        for (int n = 0; n < 16; n++) h[n] = g_hin[base * 16 + n];
        for (int s = 0; s < CLEN; s++) {
            float dv = dlt[(size_t)s * D_IN];
            float xv = xp[(size_t)s * D_IN];
            float u = dv * xv;
            float y0 = 0.f, y1 = 0.f;
#pragma unroll
            for (int n = 0; n < 16; n++) {
                float a = ex2f(dv * cn[n]);
                h[n] = a * h[n] + u * sB[s][n];
                if (n & 1) y1 += h[n] * sC[s][n];
                else       y0 += h[n] * sC[s][n];
            }
            yp[(size_t)s * D_IN] = y0 + y1 + xv * dsv;
        }
    }
}

// ------------------------------- launcher ----------------------------------
extern "C" void kernel_launch(void* const* d_in, const int* in_sizes, int n_in,
                              void* d_out, int out_size)
{
    const float* x     = (const float*)d_in[0];
    const float* gs    = (const float*)d_in[1];
    const float* w1    = (const float*)d_in[2];
    const float* dtw   = (const float*)d_in[3];
    const float* bias  = (const float*)d_in[4];
    const float* alogs = (const float*)d_in[5];
    const float* Ds    = (const float*)d_in[6];
    const float* gcw   = (const float*)d_in[7];
    const float* gcb   = (const float*)d_in[8];
    const float* gCw   = (const float*)d_in[9];
    float* y = (float*)d_out;

    k1_proj  <<<128, 256>>>(x, w1, dtw, bias, gs, gcw, gcb, gCw);
    k2_phase1<<<BATCH * 8 * NCHUNK, 128>>>(x, alogs);
    k3_combine<<<128, 256>>>(alogs);
    k4_phase3<<<BATCH * 8 * NCHUNK, 128>>>(x, alogs, Ds, y);
}

// round 3
// speedup vs baseline: 1.4485x; 1.4485x over previous
#include <cuda_runtime.h>
#include <math.h>

#define L_SEQ   2048
#define D_IN    1024
#define N_ST    16
#define BATCH   2
#define NTOK    (BATCH * L_SEQ)      // 4096
#define NCHUNK  64
#define CLEN    32                   // L_SEQ / NCHUNK
#define LOG2E   1.4426950408889634f

typedef unsigned long long ull;

// ------------------------------- scratch ----------------------------------
__device__ float g_delta[NTOK * D_IN];                     // (tok, d)
__device__ float g_bc   [NTOK * 32];                       // (tok, n)  n<16:B, n>=16:C
__device__ float g_sd   [BATCH * D_IN * NCHUNK];           // sum of delta per chunk
__device__ float g_hloc [BATCH * D_IN * NCHUNK * N_ST];    // local end state per chunk
__device__ float g_hin  [BATCH * D_IN * NCHUNK * N_ST];    // carry-in per chunk

__device__ __forceinline__ float ex2f(float x) {
    float r; asm("ex2.approx.ftz.f32 %0, %1;" : "=f"(r) : "f"(x)); return r;
}
__device__ __forceinline__ float softplusf(float z) {
    return fmaxf(z, 0.0f) + log1pf(__expf(-fabsf(z)));
}
__device__ __forceinline__ ull packf2(float lo, float hi) {
    ull d; asm("mov.b64 %0, {%1, %2};" : "=l"(d) : "r"(__float_as_uint(lo)), "r"(__float_as_uint(hi)));
    return d;
}
__device__ __forceinline__ void unpackf2(float& lo, float& hi, ull v) {
    unsigned a, b; asm("mov.b64 {%0, %1}, %2;" : "=r"(a), "=r"(b) : "l"(v));
    lo = __uint_as_float(a); hi = __uint_as_float(b);
}
__device__ __forceinline__ ull fma2(ull a, ull b, ull c) {
    ull d; asm("fma.rn.f32x2 %0, %1, %2, %3;" : "=l"(d) : "l"(a), "l"(b), "l"(c));
    return d;
}
__device__ __forceinline__ ull mul2(ull a, ull b) {
    ull d; asm("mul.rn.f32x2 %0, %1, %2;" : "=l"(d) : "l"(a), "l"(b));
    return d;
}
__device__ __forceinline__ ull add2(ull a, ull b) {
    ull d; asm("add.rn.f32x2 %0, %1, %2;" : "=l"(d) : "l"(a), "l"(b));
    return d;
}

// ------------------------- K1: projections + delta -------------------------
// 128 blocks x 256 threads, 32 tokens per block.
// Stage 1: scalar FMA, R1-proven conflict-free layout.
// Stage 2: f32x2 over r-pairs with conflict-free strides.
__global__ __launch_bounds__(256) void k1_proj(
    const float* __restrict__ x,      // (B,L,D)
    const float* __restrict__ w1,     // (64,1024)
    const float* __restrict__ dtw,    // (1024,32)
    const float* __restrict__ bias,   // (1024)
    const float* __restrict__ gs,     // (B,L)
    const float* __restrict__ gcw,    // (16)
    const float* __restrict__ gcb,    // (16)
    const float* __restrict__ gCw)    // scalar
{
    __shared__ __align__(16) union {
        struct { float x[32][65]; float w[64][65]; } s1;   // token/c-major, stride 65
        struct { float xd[32][36]; float dw[128][34]; } s2;
    } sm;

    const int tid = threadIdx.x;
    const int tokbase = blockIdx.x * 32;

    const int kk = tid & 63, q = tid >> 6;           // coop-load coords
    const int ct = tid & 15, tt = tid >> 4;          // compute coords
    const int c0 = ct * 4, t0 = tt * 2;

    // ---- stage 1: x_dbl = x @ W1^T (scalar, conflict-free) ----
    float acc[4][2];
#pragma unroll
    for (int i = 0; i < 4; i++) { acc[i][0] = 0.f; acc[i][1] = 0.f; }

    for (int kt = 0; kt < 16; kt++) {
        const int k0 = kt * 64;
#pragma unroll
        for (int r = 0; r < 8; r++) {
            int t = q + r * 4;
            sm.s1.x[t][kk] = x[(size_t)(tokbase + t) * D_IN + k0 + kk];
        }
#pragma unroll
        for (int r = 0; r < 16; r++) {
            int c = q + r * 4;
            sm.s1.w[c][kk] = w1[(size_t)c * D_IN + k0 + kk];
        }
        __syncthreads();
#pragma unroll 16
        for (int k2 = 0; k2 < 64; k2++) {
            float xv0 = sm.s1.x[t0][k2];
            float xv1 = sm.s1.x[t0 + 1][k2];
#pragma unroll
            for (int i = 0; i < 4; i++) {
                float wv = sm.s1.w[c0 + i][k2];
                acc[i][0] += wv * xv0;
                acc[i][1] += wv * xv1;
            }
        }
        __syncthreads();
    }

    // ---- writeback: c<32 -> smem xd; c>=32 -> B / corrected C to gmem ----
    {
        const float gCwv = gCw[0];
#pragma unroll
        for (int i = 0; i < 4; i++) {
            int c = c0 + i;
            if (c < 32) {
                sm.s2.xd[t0][c]     = acc[i][0];
                sm.s2.xd[t0 + 1][c] = acc[i][1];
            } else {
                int n = c - 32;
#pragma unroll
                for (int j = 0; j < 2; j++) {
                    int tok = tokbase + t0 + j;
                    int b = tok >> 11, l = tok & 2047;
                    float v = acc[i][j];
                    if (n >= 16) {
                        int m = n - 16;
                        float ge = gs[b * 2048 + m * 128 + (l >> 4)] * gcw[l & 15] + gcb[l & 15];
                        v += gCwv * ge;
                    }
                    g_bc[(size_t)tok * 32 + n] = v;
                }
            }
        }
    }

    // ---- stage 2: delta = softplus(xd @ dtW^T + bias), f32x2 over r-pairs ----
    const int dlane = tid & 127, th = tid >> 7;
    for (int db = 0; db < 8; db++) {
        __syncthreads();
#pragma unroll
        for (int i = 0; i < 16; i++) {
            int idx = tid + i * 256;                 // 0..4095 = 128 d * 32 r
            sm.s2.dw[idx >> 5][idx & 31] =
                dtw[(size_t)(db * 128 + (idx >> 5)) * 32 + (idx & 31)];
        }
        __syncthreads();

        // per-thread weights: 16 natural r-pairs (LDS.64, 2-way max)
        ull w2r[16];
        const ull* wrow = (const ull*)&sm.s2.dw[dlane][0];
#pragma unroll
        for (int k = 0; k < 16; k++) w2r[k] = wrow[k];
        const int d = db * 128 + dlane;
        const float bz = bias[d];

        for (int t = th * 16; t < th * 16 + 16; t++) {
            const ulonglong2* xrow = (const ulonglong2*)&sm.s2.xd[t][0];  // broadcast
            ull a2 = 0ull, b2 = 0ull;
#pragma unroll
            for (int k = 0; k < 8; k++) {
                ulonglong2 qv = xrow[k];
                a2 = fma2(w2r[2*k],     qv.x, a2);
                b2 = fma2(w2r[2*k + 1], qv.y, b2);
            }
            float lo, hi; unpackf2(lo, hi, add2(a2, b2));
            g_delta[(size_t)(tokbase + t) * D_IN + d] = softplusf(lo + hi + bz);
        }
    }
}

// --------------------- K2: scan phase 1 (chunk summaries) ------------------
__global__ __launch_bounds__(128) void k2_phase1(
    const float* __restrict__ x, const float* __restrict__ alogs)
{
    __shared__ __align__(16) float sB[CLEN][16];
    const int tid = threadIdx.x;
    const int bid = blockIdx.x;
    const int ch = bid & (NCHUNK - 1);
    const int dg = (bid >> 6) & 7;
    const int b  = bid >> 9;
    const int d  = dg * 128 + tid;
    const int l0 = ch * CLEN;

    {   // 32 rows x 4 float4 = 128 loads, one per thread
        int s = tid >> 2, qd = tid & 3;
        ((float4*)&sB[s][0])[qd] = *(const float4*)&g_bc[(size_t)(b * 2048 + l0 + s) * 32 + qd * 4];
    }
    __syncthreads();

    float cn[16];
#pragma unroll
    for (int n = 0; n < 16; n++)
        cn[n] = -__expf(alogs[(size_t)d * 16 + n]) * LOG2E;
    bool fast = true;
#pragma unroll
    for (int n = 1; n < 16; n++) {
        float want = (float)(n + 1) * cn[0];
        fast = fast && (fabsf(cn[n] - want) <= 1e-4f * fabsf(want));
    }

    float sd = 0.f;
    const float* dlt = &g_delta[(size_t)(b * 2048 + l0) * D_IN + d];
    const float* xp  = &x[(size_t)(b * 2048 + l0) * D_IN + d];
    const size_t base = (size_t)(b * 1024 + d) * NCHUNK + ch;

    if (fast) {
        const float c0 = cn[0];
        ull h2[8];
#pragma unroll
        for (int k = 0; k < 8; k++) h2[k] = 0ull;
        float dv = dlt[0], xv = xp[0];
#pragma unroll 2
        for (int s = 0; s < CLEN; s++) {
            float dvn = 0.f, xvn = 0.f;
            if (s + 1 < CLEN) { dvn = dlt[(size_t)(s+1) * D_IN]; xvn = xp[(size_t)(s+1) * D_IN]; }
            sd += dv;
            float e  = ex2f(dv * c0);
            float e2 = e * e;
            float u  = dv * xv;
            ull uu = packf2(u, u);
            ull dd = packf2(e2, e2);
            ull P0 = packf2(e, e2);
            ull D4 = mul2(dd, dd);
            ull P1 = mul2(P0, dd);
            ull D8 = mul2(D4, D4);
            ull P2 = mul2(P0, D4);
            ull P3 = mul2(P1, D4);
            ull P4 = mul2(P0, D8);
            ull P5 = mul2(P1, D8);
            ull P6 = mul2(P2, D8);
            ull P7 = mul2(P3, D8);
            const ulonglong2* B2 = (const ulonglong2*)&sB[s][0];
            ulonglong2 b0 = B2[0], b1 = B2[1], b2v = B2[2], b3 = B2[3];
            h2[0] = fma2(P0, h2[0], mul2(uu, b0.x));
            h2[1] = fma2(P1, h2[1], mul2(uu, b0.y));
            h2[2] = fma2(P2, h2[2], mul2(uu, b1.x));
            h2[3] = fma2(P3, h2[3], mul2(uu, b1.y));
            h2[4] = fma2(P4, h2[4], mul2(uu, b2v.x));
            h2[5] = fma2(P5, h2[5], mul2(uu, b2v.y));
            h2[6] = fma2(P6, h2[6], mul2(uu, b3.x));
            h2[7] = fma2(P7, h2[7], mul2(uu, b3.y));
            dv = dvn; xv = xvn;
        }
        g_sd[base] = sd;
#pragma unroll
        for (int k = 0; k < 8; k++) *(ull*)&g_hloc[base * 16 + 2 * k] = h2[k];
    } else {
        float h[16];
#pragma unroll
        for (int n = 0; n < 16; n++) h[n] = 0.f;
        for (int s = 0; s < CLEN; s++) {
            float dv = dlt[(size_t)s * D_IN];
            float xv = xp[(size_t)s * D_IN];
            sd += dv;
            float u = dv * xv;
#pragma unroll
            for (int n = 0; n < 16; n++) {
                float a = ex2f(dv * cn[n]);
                h[n] = a * h[n] + u * sB[s][n];
            }
        }
        g_sd[base] = sd;
#pragma unroll
        for (int n = 0; n < 16; n++) g_hloc[base * 16 + n] = h[n];
    }
}

// ----------------------- K3: combine chunk carries -------------------------
__global__ __launch_bounds__(256) void k3_combine(const float* __restrict__ alogs)
{
    const int tid = blockIdx.x * 256 + threadIdx.x;      // 0..32767
    const int n = tid & 15;
    const int bd = tid >> 4;                             // b*1024 + d
    const int d = bd & 1023;
    const float cnf = -__expf(alogs[(size_t)d * 16 + n]) * LOG2E;

    const size_t base = (size_t)bd * NCHUNK;
    float H = 0.f;
    float sd_n = g_sd[base];
    float hl_n = g_hloc[base * 16 + n];
#pragma unroll 4
    for (int c = 0; c < NCHUNK; c++) {
        float sdv = sd_n, hl = hl_n;
        if (c + 1 < NCHUNK) {
            sd_n = g_sd[base + c + 1];
            hl_n = g_hloc[(base + c + 1) * 16 + n];
        }
        g_hin[(base + c) * 16 + n] = H;
        H = ex2f(sdv * cnf) * H + hl;
    }
}

// ----------------------- K4: scan phase 3 (emit y) --------------------------
__global__ __launch_bounds__(128) void k4_phase3(
    const float* __restrict__ x, const float* __restrict__ alogs,
    const float* __restrict__ Ds, float* __restrict__ y)
{
    __shared__ __align__(16) float sB[CLEN][16];
    __shared__ __align__(16) float sC[CLEN][16];
    const int tid = threadIdx.x;
    const int bid = blockIdx.x;
    const int ch = bid & (NCHUNK - 1);
    const int dg = (bid >> 6) & 7;
    const int b  = bid >> 9;
    const int d  = dg * 128 + tid;
    const int l0 = ch * CLEN;

#pragma unroll
    for (int i = 0; i < 2; i++) {
        int idx = tid + i * 128;                 // 0..255: 32 rows x 8 float4
        int s = idx >> 3, qd = idx & 7;
        float4 v = *(const float4*)&g_bc[(size_t)(b * 2048 + l0 + s) * 32 + qd * 4];
        if (qd < 4) ((float4*)&sB[s][0])[qd] = v;
        else        ((float4*)&sC[s][0])[qd - 4] = v;
    }
    __syncthreads();

    float cn[16];
#pragma unroll
    for (int n = 0; n < 16; n++)
        cn[n] = -__expf(alogs[(size_t)d * 16 + n]) * LOG2E;
    bool fast = true;
#pragma unroll
    for (int n = 1; n < 16; n++) {
        float want = (float)(n + 1) * cn[0];
        fast = fast && (fabsf(cn[n] - want) <= 1e-4f * fabsf(want));
    }

    const size_t base = (size_t)(b * 1024 + d) * NCHUNK + ch;
    const float dsv = Ds[d];
    const float* dlt = &g_delta[(size_t)(b * 2048 + l0) * D_IN + d];
    const float* xp  = &x[(size_t)(b * 2048 + l0) * D_IN + d];
    float* yp        = &y[(size_t)(b * 2048 + l0) * D_IN + d];

    if (fast) {
        const float c0 = cn[0];
        ull h2[8];
#pragma unroll
        for (int k = 0; k < 8; k++) h2[k] = *(const ull*)&g_hin[base * 16 + 2 * k];
        float dv = dlt[0], xv = xp[0];
#pragma unroll 2
        for (int s = 0; s < CLEN; s++) {
            float dvn = 0.f, xvn = 0.f;
            if (s + 1 < CLEN) { dvn = dlt[(size_t)(s+1) * D_IN]; xvn = xp[(size_t)(s+1) * D_IN]; }
            float e  = ex2f(dv * c0);
            float e2 = e * e;
            float u  = dv * xv;
            ull uu = packf2(u, u);
            ull dd = packf2(e2, e2);
            ull P0 = packf2(e, e2);
            ull D4 = mul2(dd, dd);
            ull P1 = mul2(P0, dd);
            ull D8 = mul2(D4, D4);
            ull P2 = mul2(P0, D4);
            ull P3 = mul2(P1, D4);
            ull P4 = mul2(P0, D8);
            ull P5 = mul2(P1, D8);
            ull P6 = mul2(P2, D8);
            ull P7 = mul2(P3, D8);
            const ulonglong2* B2 = (const ulonglong2*)&sB[s][0];
            const ulonglong2* C2 = (const ulonglong2*)&sC[s][0];
            ulonglong2 b0 = B2[0], b1 = B2[1], b2v = B2[2], b3 = B2[3];
            ulonglong2 cc0 = C2[0], cc1 = C2[1], cc2 = C2[2], cc3 = C2[3];
            ull y2a, y2b;
            h2[0] = fma2(P0, h2[0], mul2(uu, b0.x));  y2a = mul2(h2[0], cc0.x);
            h2[1] = fma2(P1, h2[1], mul2(uu, b0.y));  y2b = mul2(h2[1], cc0.y);
            h2[2] = fma2(P2, h2[2], mul2(uu, b1.x));  y2a = fma2(h2[2], cc1.x, y2a);
            h2[3] = fma2(P3, h2[3], mul2(uu, b1.y));  y2b = fma2(h2[3], cc1.y, y2b);
            h2[4] = fma2(P4, h2[4], mul2(uu, b2v.x)); y2a = fma2(h2[4], cc2.x, y2a);
            h2[5] = fma2(P5, h2[5], mul2(uu, b2v.y)); y2b = fma2(h2[5], cc2.y, y2b);
            h2[6] = fma2(P6, h2[6], mul2(uu, b3.x));  y2a = fma2(h2[6], cc3.x, y2a);
            h2[7] = fma2(P7, h2[7], mul2(uu, b3.y));  y2b = fma2(h2[7], cc3.y, y2b);
            float ylo, yhi; unpackf2(ylo, yhi, add2(y2a, y2b));
            yp[(size_t)s * D_IN] = ylo + yhi + xv * dsv;
            dv = dvn; xv = xvn;
        }
    } else {
        float h[16];
#pragma unroll
        for (int n = 0; n < 16; n++) h[n] = g_hin[base * 16 + n];
        for (int s = 0; s < CLEN; s++) {
            float dv = dlt[(size_t)s * D_IN];
            float xv = xp[(size_t)s * D_IN];
            float u = dv * xv;
            float y0 = 0.f, y1 = 0.f;
#pragma unroll
            for (int n = 0; n < 16; n++) {
                float a = ex2f(dv * cn[n]);
                h[n] = a * h[n] + u * sB[s][n];
                if (n & 1) y1 += h[n] * sC[s][n];
                else       y0 += h[n] * sC[s][n];
            }
            yp[(size_t)s * D_IN] = y0 + y1 + xv * dsv;
        }
    }
}

// ------------------------------- launcher ----------------------------------
extern "C" void kernel_launch(void* const* d_in, const int* in_sizes, int n_in,
                              void* d_out, int out_size)
{
    const float* x     = (const float*)d_in[0];
    const float* gs    = (const float*)d_in[1];
    const float* w1    = (const float*)d_in[2];
    const float* dtw   = (const float*)d_in[3];
    const float* bias  = (const float*)d_in[4];
    const float* alogs = (const float*)d_in[5];
    const float* Ds    = (const float*)d_in[6];
    const float* gcw   = (const float*)d_in[7];
    const float* gcb   = (const float*)d_in[8];
    const float* gCw   = (const float*)d_in[9];
    float* y = (float*)d_out;

    k1_proj  <<<128, 256>>>(x, w1, dtw, bias, gs, gcw, gcb, gCw);
    k2_phase1<<<BATCH * 8 * NCHUNK, 128>>>(x, alogs);
    k3_combine<<<128, 256>>>(alogs);
    k4_phase3<<<BATCH * 8 * NCHUNK, 128>>>(x, alogs, Ds, y);
}

// round 5
// speedup vs baseline: 1.7022x; 1.1751x over previous
#include <cuda_runtime.h>
#include <math.h>

#define L_SEQ   2048
#define D_IN    1024
#define N_ST    16
#define BATCH   2
#define NTOK    (BATCH * L_SEQ)      // 4096
#define NCHUNK  64
#define CLEN    32                   // L_SEQ / NCHUNK
#define KSPLIT  8
#define LOG2E   1.4426950408889634f

typedef unsigned long long ull;

// ------------------------------- scratch ----------------------------------
__device__ float g_part [KSPLIT * NTOK * 64];              // split-K partials
__device__ float g_delta[NTOK * D_IN];                     // (tok, d)
__device__ float g_bc   [NTOK * 32];                       // (tok, n)  n<16:B, n>=16:C
__device__ float g_sd   [BATCH * D_IN * NCHUNK];
__device__ float g_hloc [BATCH * D_IN * NCHUNK * N_ST];
__device__ float g_hin  [BATCH * D_IN * NCHUNK * N_ST];

__device__ __forceinline__ float ex2f(float x) {
    float r; asm("ex2.approx.ftz.f32 %0, %1;" : "=f"(r) : "f"(x)); return r;
}
__device__ __forceinline__ float softplusf(float z) {
    return fmaxf(z, 0.0f) + log1pf(__expf(-fabsf(z)));
}
__device__ __forceinline__ ull packf2(float lo, float hi) {
    ull d; asm("mov.b64 %0, {%1, %2};" : "=l"(d) : "r"(__float_as_uint(lo)), "r"(__float_as_uint(hi)));
    return d;
}
__device__ __forceinline__ void unpackf2(float& lo, float& hi, ull v) {
    unsigned a, b; asm("mov.b64 {%0, %1}, %2;" : "=r"(a), "=r"(b) : "l"(v));
    lo = __uint_as_float(a); hi = __uint_as_float(b);
}
__device__ __forceinline__ ull fma2(ull a, ull b, ull c) {
    ull d; asm("fma.rn.f32x2 %0, %1, %2, %3;" : "=l"(d) : "l"(a), "l"(b), "l"(c));
    return d;
}
__device__ __forceinline__ ull mul2(ull a, ull b) {
    ull d; asm("mul.rn.f32x2 %0, %1, %2;" : "=l"(d) : "l"(a), "l"(b));
    return d;
}
__device__ __forceinline__ ull add2(ull a, ull b) {
    ull d; asm("add.rn.f32x2 %0, %1, %2;" : "=l"(d) : "l"(a), "l"(b));
    return d;
}

// ------------------ K1a: stage-1 GEMM, split-K, k-pair f32x2 ----------------
// 512 blocks = 64 token-groups(64 tok) x 8 k-splits(128 k). 128 threads.
// Thread tile: 4 tokens (t = tt + 16i) x 8 outputs (c = ct + 8j).
__global__ __launch_bounds__(128) void k1a_gemm(
    const float* __restrict__ x,      // (4096, 1024)
    const float* __restrict__ w1)     // (64, 1024)
{
    __shared__ __align__(16) float xs[64][68];
    __shared__ __align__(16) float ws[64][68];

    const int tid = threadIdx.x;
    const int tg = blockIdx.x & 63, ks = blockIdx.x >> 6;
    const int tokbase = tg * 64;
    const int kbase = ks * 128;
    const int ct = tid & 7, tt = tid >> 3;

    ull acc[4][8];
#pragma unroll
    for (int i = 0; i < 4; i++)
#pragma unroll
        for (int j = 0; j < 8; j++) acc[i][j] = 0ull;

#pragma unroll 1
    for (int kt = 0; kt < 2; kt++) {
        const int k0 = kbase + kt * 64;
#pragma unroll
        for (int r = 0; r < 8; r++) {
            int f = tid + r * 128;               // 1024 float4 = 64 rows x 16
            int row = f >> 4, c4 = f & 15;
            *(float4*)&xs[row][c4 * 4] =
                *(const float4*)&x[(size_t)(tokbase + row) * D_IN + k0 + c4 * 4];
        }
#pragma unroll
        for (int r = 0; r < 8; r++) {
            int f = tid + r * 128;
            int row = f >> 4, c4 = f & 15;
            *(float4*)&ws[row][c4 * 4] =
                *(const float4*)&w1[(size_t)row * D_IN + k0 + c4 * 4];
        }
        __syncthreads();

#pragma unroll 8
        for (int kp = 0; kp < 32; kp++) {
            ull xv[4], wv[8];
#pragma unroll
            for (int i = 0; i < 4; i++) xv[i] = *(const ull*)&xs[tt + 16 * i][2 * kp];
#pragma unroll
            for (int j = 0; j < 8; j++) wv[j] = *(const ull*)&ws[ct + 8 * j][2 * kp];
#pragma unroll
            for (int i = 0; i < 4; i++)
#pragma unroll
                for (int j = 0; j < 8; j++)
                    acc[i][j] = fma2(xv[i], wv[j], acc[i][j]);
        }
        __syncthreads();
    }

    // horizontal reduce (k-pair lo+hi), stage through smem, coalesced store
#pragma unroll
    for (int i = 0; i < 4; i++)
#pragma unroll
        for (int j = 0; j < 8; j++) {
            float lo, hi; unpackf2(lo, hi, acc[i][j]);
            xs[tt + 16 * i][ct + 8 * j] = lo + hi;
        }
    __syncthreads();
#pragma unroll
    for (int r = 0; r < 8; r++) {
        int f = tid + r * 128;                   // 1024 f4 = 64 rows x 16
        int row = f >> 4, c4 = f & 15;
        *(float4*)&g_part[((size_t)ks * NTOK + tokbase + row) * 64 + c4 * 4] =
            *(float4*)&xs[row][c4 * 4];
    }
}

// ----------- K1b: combine partials -> delta GEMM + B/C epilogue -------------
// 1024 blocks = 128 token-groups(32 tok) x 8 d-groups(128 d). 128 threads.
__global__ __launch_bounds__(128) void k1b_delta(
    const float* __restrict__ dtw,    // (1024, 32)
    const float* __restrict__ bias,   // (1024)
    const float* __restrict__ gs,     // (B, L)
    const float* __restrict__ gcw,    // (16)
    const float* __restrict__ gcb,    // (16)
    const float* __restrict__ gCw)    // scalar
{
    __shared__ __align__(16) float xd[32][36];
    __shared__ __align__(16) float dw[128][34];   // stride 34: 2-way max on LDS.64

    const int tid = threadIdx.x;
    const int dg = blockIdx.x & 7, tg = blockIdx.x >> 3;
    const int tokbase = tg * 32;

    // sum split-K partials for dts_r (c < 32)
#pragma unroll
    for (int r = 0; r < 2; r++) {
        int f = tid + r * 128;                   // 256 f4 = 32 rows x 8
        int row = f >> 3, c4 = f & 7;
        float4 s = make_float4(0.f, 0.f, 0.f, 0.f);
#pragma unroll
        for (int k = 0; k < KSPLIT; k++) {
            float4 v = *(const float4*)&g_part[((size_t)k * NTOK + tokbase + row) * 64 + c4 * 4];
            s.x += v.x; s.y += v.y; s.z += v.z; s.w += v.w;
        }
        *(float4*)&xd[row][c4 * 4] = s;
    }
    // load dtW slice — float2 (dw row stride 136B: 8B-aligned always, NOT 16B)
#pragma unroll
    for (int r = 0; r < 16; r++) {
        int f = tid + r * 128;                   // 2048 float2 = 128 rows x 16
        int row = f >> 4, c2 = f & 15;
        *(float2*)&dw[row][c2 * 2] =
            *(const float2*)&dtw[(size_t)(dg * 128 + row) * 32 + c2 * 2];
    }
    // dg==0 blocks also emit B and corrected C for their tokens
    if (dg == 0) {
        const float gCwv = gCw[0];
#pragma unroll
        for (int r = 0; r < 8; r++) {
            int f = tid + r * 128;               // 1024 = 32 tok x 32 n
            int t = f >> 5, n = f & 31;
            float s = 0.f;
#pragma unroll
            for (int k = 0; k < KSPLIT; k++)
                s += g_part[((size_t)k * NTOK + tokbase + t) * 64 + 32 + n];
            int tok = tokbase + t;
            int b = tok >> 11, l = tok & 2047;
            if (n >= 16) {
                int m = n - 16;
                s += gCwv * (gs[b * 2048 + m * 128 + (l >> 4)] * gcw[l & 15] + gcb[l & 15]);
            }
            g_bc[(size_t)tok * 32 + n] = s;
        }
    }
    __syncthreads();

    // delta GEMM: f32x2 over r-pairs, w cached in regs
    ull w2r[16];
    const ull* wrow = (const ull*)&dw[tid][0];
#pragma unroll
    for (int k = 0; k < 16; k++) w2r[k] = wrow[k];
    const int d = dg * 128 + tid;
    const float bz = bias[d];

#pragma unroll 4
    for (int t = 0; t < 32; t++) {
        const ulonglong2* xrow = (const ulonglong2*)&xd[t][0];   // broadcast
        ull a2 = 0ull, b2 = 0ull;
#pragma unroll
        for (int k = 0; k < 8; k++) {
            ulonglong2 qv = xrow[k];
            a2 = fma2(w2r[2 * k],     qv.x, a2);
            b2 = fma2(w2r[2 * k + 1], qv.y, b2);
        }
        float lo, hi; unpackf2(lo, hi, add2(a2, b2));
        g_delta[(size_t)(tokbase + t) * D_IN + d] = softplusf(lo + hi + bz);
    }
}

// --------------------- K2: scan phase 1 (chunk summaries) ------------------
__global__ __launch_bounds__(128) void k2_phase1(
    const float* __restrict__ x, const float* __restrict__ alogs)
{
    __shared__ __align__(16) float sB[CLEN][16];
    const int tid = threadIdx.x;
    const int bid = blockIdx.x;
    const int ch = bid & (NCHUNK - 1);
    const int dg = (bid >> 6) & 7;
    const int b  = bid >> 9;
    const int d  = dg * 128 + tid;
    const int l0 = ch * CLEN;

    {
        int s = tid >> 2, qd = tid & 3;
        ((float4*)&sB[s][0])[qd] = *(const float4*)&g_bc[(size_t)(b * 2048 + l0 + s) * 32 + qd * 4];
    }
    __syncthreads();

    float cn[16];
#pragma unroll
    for (int n = 0; n < 16; n++)
        cn[n] = -__expf(alogs[(size_t)d * 16 + n]) * LOG2E;
    bool fast = true;
#pragma unroll
    for (int n = 1; n < 16; n++) {
        float want = (float)(n + 1) * cn[0];
        fast = fast && (fabsf(cn[n] - want) <= 1e-4f * fabsf(want));
    }

    float sd = 0.f;
    const float* dlt = &g_delta[(size_t)(b * 2048 + l0) * D_IN + d];
    const float* xp  = &x[(size_t)(b * 2048 + l0) * D_IN + d];
    const size_t base = (size_t)(b * 1024 + d) * NCHUNK + ch;

    if (fast) {
        const float c0 = cn[0];
        ull h2[8];
#pragma unroll
        for (int k = 0; k < 8; k++) h2[k] = 0ull;
        float dv = dlt[0], xv = xp[0];
#pragma unroll 2
        for (int s = 0; s < CLEN; s++) {
            float dvn = 0.f, xvn = 0.f;
            if (s + 1 < CLEN) { dvn = dlt[(size_t)(s+1) * D_IN]; xvn = xp[(size_t)(s+1) * D_IN]; }
            sd += dv;
            float e  = ex2f(dv * c0);
            float e2 = e * e;
            float u  = dv * xv;
            ull uu = packf2(u, u);
            ull dd = packf2(e2, e2);
            ull P0 = packf2(e, e2);
            ull D4 = mul2(dd, dd);
            ull P1 = mul2(P0, dd);
            ull D8 = mul2(D4, D4);
            ull P2 = mul2(P0, D4);
            ull P3 = mul2(P1, D4);
            ull P4 = mul2(P0, D8);
            ull P5 = mul2(P1, D8);
            ull P6 = mul2(P2, D8);
            ull P7 = mul2(P3, D8);
            const ulonglong2* B2 = (const ulonglong2*)&sB[s][0];
            ulonglong2 b0 = B2[0], b1 = B2[1], b2v = B2[2], b3 = B2[3];
            h2[0] = fma2(P0, h2[0], mul2(uu, b0.x));
            h2[1] = fma2(P1, h2[1], mul2(uu, b0.y));
            h2[2] = fma2(P2, h2[2], mul2(uu, b1.x));
            h2[3] = fma2(P3, h2[3], mul2(uu, b1.y));
            h2[4] = fma2(P4, h2[4], mul2(uu, b2v.x));
            h2[5] = fma2(P5, h2[5], mul2(uu, b2v.y));
            h2[6] = fma2(P6, h2[6], mul2(uu, b3.x));
            h2[7] = fma2(P7, h2[7], mul2(uu, b3.y));
            dv = dvn; xv = xvn;
        }
        g_sd[base] = sd;
#pragma unroll
        for (int k = 0; k < 8; k++) *(ull*)&g_hloc[base * 16 + 2 * k] = h2[k];
    } else {
        float h[16];
#pragma unroll
        for (int n = 0; n < 16; n++) h[n] = 0.f;
        for (int s = 0; s < CLEN; s++) {
            float dv = dlt[(size_t)s * D_IN];
            float xv = xp[(size_t)s * D_IN];
            sd += dv;
            float u = dv * xv;
#pragma unroll
            for (int n = 0; n < 16; n++) {
                float a = ex2f(dv * cn[n]);
                h[n] = a * h[n] + u * sB[s][n];
            }
        }
        g_sd[base] = sd;
#pragma unroll
        for (int n = 0; n < 16; n++) g_hloc[base * 16 + n] = h[n];
    }
}

// ----------------------- K3: combine chunk carries -------------------------
__global__ __launch_bounds__(256) void k3_combine(const float* __restrict__ alogs)
{
    const int tid = blockIdx.x * 256 + threadIdx.x;      // 0..32767
    const int n = tid & 15;
    const int bd = tid >> 4;
    const int d = bd & 1023;
    const float cnf = -__expf(alogs[(size_t)d * 16 + n]) * LOG2E;

    const size_t base = (size_t)bd * NCHUNK;
    float H = 0.f;
    float sd_n = g_sd[base];
    float hl_n = g_hloc[base * 16 + n];
#pragma unroll 4
    for (int c = 0; c < NCHUNK; c++) {
        float sdv = sd_n, hl = hl_n;
        if (c + 1 < NCHUNK) {
            sd_n = g_sd[base + c + 1];
            hl_n = g_hloc[(base + c + 1) * 16 + n];
        }
        g_hin[(base + c) * 16 + n] = H;
        H = ex2f(sdv * cnf) * H + hl;
    }
}

// ----------------------- K4: scan phase 3 (emit y) --------------------------
__global__ __launch_bounds__(128) void k4_phase3(
    const float* __restrict__ x, const float* __restrict__ alogs,
    const float* __restrict__ Ds, float* __restrict__ y)
{
    __shared__ __align__(16) float sB[CLEN][16];
    __shared__ __align__(16) float sC[CLEN][16];
    const int tid = threadIdx.x;
    const int bid = blockIdx.x;
    const int ch = bid & (NCHUNK - 1);
    const int dg = (bid >> 6) & 7;
    const int b  = bid >> 9;
    const int d  = dg * 128 + tid;
    const int l0 = ch * CLEN;

#pragma unroll
    for (int i = 0; i < 2; i++) {
        int idx = tid + i * 128;
        int s = idx >> 3, qd = idx & 7;
        float4 v = *(const float4*)&g_bc[(size_t)(b * 2048 + l0 + s) * 32 + qd * 4];
        if (qd < 4) ((float4*)&sB[s][0])[qd] = v;
        else        ((float4*)&sC[s][0])[qd - 4] = v;
    }
    __syncthreads();

    float cn[16];
#pragma unroll
    for (int n = 0; n < 16; n++)
        cn[n] = -__expf(alogs[(size_t)d * 16 + n]) * LOG2E;
    bool fast = true;
#pragma unroll
    for (int n = 1; n < 16; n++) {
        float want = (float)(n + 1) * cn[0];
        fast = fast && (fabsf(cn[n] - want) <= 1e-4f * fabsf(want));
    }

    const size_t base = (size_t)(b * 1024 + d) * NCHUNK + ch;
    const float dsv = Ds[d];
    const float* dlt = &g_delta[(size_t)(b * 2048 + l0) * D_IN + d];
    const float* xp  = &x[(size_t)(b * 2048 + l0) * D_IN + d];
    float* yp        = &y[(size_t)(b * 2048 + l0) * D_IN + d];

    if (fast) {
        const float c0 = cn[0];
        ull h2[8];
#pragma unroll
        for (int k = 0; k < 8; k++) h2[k] = *(const ull*)&g_hin[base * 16 + 2 * k];
        float dv = dlt[0], xv = xp[0];
#pragma unroll 2
        for (int s = 0; s < CLEN; s++) {
            float dvn = 0.f, xvn = 0.f;
            if (s + 1 < CLEN) { dvn = dlt[(size_t)(s+1) * D_IN]; xvn = xp[(size_t)(s+1) * D_IN]; }
            float e  = ex2f(dv * c0);
            float e2 = e * e;
            float u  = dv * xv;
            ull uu = packf2(u, u);
            ull dd = packf2(e2, e2);
            ull P0 = packf2(e, e2);
            ull D4 = mul2(dd, dd);
            ull P1 = mul2(P0, dd);
            ull D8 = mul2(D4, D4);
            ull P2 = mul2(P0, D4);
            ull P3 = mul2(P1, D4);
            ull P4 = mul2(P0, D8);
            ull P5 = mul2(P1, D8);
            ull P6 = mul2(P2, D8);
            ull P7 = mul2(P3, D8);
            const ulonglong2* B2 = (const ulonglong2*)&sB[s][0];
            const ulonglong2* C2 = (const ulonglong2*)&sC[s][0];
            ulonglong2 b0 = B2[0], b1 = B2[1], b2v = B2[2], b3 = B2[3];
            ulonglong2 cc0 = C2[0], cc1 = C2[1], cc2 = C2[2], cc3 = C2[3];
            ull y2a, y2b;
            h2[0] = fma2(P0, h2[0], mul2(uu, b0.x));  y2a = mul2(h2[0], cc0.x);
            h2[1] = fma2(P1, h2[1], mul2(uu, b0.y));  y2b = mul2(h2[1], cc0.y);
            h2[2] = fma2(P2, h2[2], mul2(uu, b1.x));  y2a = fma2(h2[2], cc1.x, y2a);
            h2[3] = fma2(P3, h2[3], mul2(uu, b1.y));  y2b = fma2(h2[3], cc1.y, y2b);
            h2[4] = fma2(P4, h2[4], mul2(uu, b2v.x)); y2a = fma2(h2[4], cc2.x, y2a);
            h2[5] = fma2(P5, h2[5], mul2(uu, b2v.y)); y2b = fma2(h2[5], cc2.y, y2b);
            h2[6] = fma2(P6, h2[6], mul2(uu, b3.x));  y2a = fma2(h2[6], cc3.x, y2a);
            h2[7] = fma2(P7, h2[7], mul2(uu, b3.y));  y2b = fma2(h2[7], cc3.y, y2b);
            float ylo, yhi; unpackf2(ylo, yhi, add2(y2a, y2b));
            yp[(size_t)s * D_IN] = ylo + yhi + xv * dsv;
            dv = dvn; xv = xvn;
        }
    } else {
        float h[16];
#pragma unroll
        for (int n = 0; n < 16; n++) h[n] = g_hin[base * 16 + n];
        for (int s = 0; s < CLEN; s++) {
            float dv = dlt[(size_t)s * D_IN];
            float xv = xp[(size_t)s * D_IN];
            float u = dv * xv;
            float y0 = 0.f, y1 = 0.f;
#pragma unroll
            for (int n = 0; n < 16; n++) {
                float a = ex2f(dv * cn[n]);
                h[n] = a * h[n] + u * sB[s][n];
                if (n & 1) y1 += h[n] * sC[s][n];
                else       y0 += h[n] * sC[s][n];
            }
            yp[(size_t)s * D_IN] = y0 + y1 + xv * dsv;
        }
    }
}

// ------------------------------- launcher ----------------------------------
extern "C" void kernel_launch(void* const* d_in, const int* in_sizes, int n_in,
                              void* d_out, int out_size)
{
    const float* x     = (const float*)d_in[0];
    const float* gs    = (const float*)d_in[1];
    const float* w1    = (const float*)d_in[2];
    const float* dtw   = (const float*)d_in[3];
    const float* bias  = (const float*)d_in[4];
    const float* alogs = (const float*)d_in[5];
    const float* Ds    = (const float*)d_in[6];
    const float* gcw   = (const float*)d_in[7];
    const float* gcb   = (const float*)d_in[8];
    const float* gCw   = (const float*)d_in[9];
    float* y = (float*)d_out;

    k1a_gemm <<<64 * KSPLIT, 128>>>(x, w1);
    k1b_delta<<<128 * 8, 128>>>(dtw, bias, gs, gcw, gcb, gCw);
    k2_phase1<<<BATCH * 8 * NCHUNK, 128>>>(x, alogs);
    k3_combine<<<128, 256>>>(alogs);
    k4_phase3<<<BATCH * 8 * NCHUNK, 128>>>(x, alogs, Ds, y);
}

// round 6
// speedup vs baseline: 1.9041x; 1.1186x over previous
#include <cuda_runtime.h>
#include <math.h>

#define L_SEQ   2048
#define D_IN    1024
#define N_ST    16
#define BATCH   2
#define NTOK    (BATCH * L_SEQ)      // 4096
#define NCHUNK  64
#define CLEN    32                   // L_SEQ / NCHUNK
#define NSEG    8
#define SEGLEN  8                    // NCHUNK / NSEG
#define KSPLIT  8
#define LOG2E   1.4426950408889634f

typedef unsigned long long ull;

// ------------------------------- scratch ----------------------------------
__device__ float g_part [KSPLIT * NTOK * 64];              // split-K partials
__device__ float g_delta[NTOK * D_IN];                     // (tok, d)
__device__ float g_bc   [NTOK * 32];                       // (tok, n)  n<16:B, n>=16:C
__device__ float g_sd   [BATCH * D_IN * NCHUNK];
__device__ float g_hloc [BATCH * D_IN * NCHUNK * N_ST];
__device__ float g_hin  [BATCH * D_IN * NCHUNK * N_ST];

__device__ __forceinline__ float ex2f(float x) {
    float r; asm("ex2.approx.ftz.f32 %0, %1;" : "=f"(r) : "f"(x)); return r;
}
__device__ __forceinline__ float softplusf(float z) {
    return fmaxf(z, 0.0f) + log1pf(__expf(-fabsf(z)));
}
__device__ __forceinline__ ull packf2(float lo, float hi) {
    ull d; asm("mov.b64 %0, {%1, %2};" : "=l"(d) : "r"(__float_as_uint(lo)), "r"(__float_as_uint(hi)));
    return d;
}
__device__ __forceinline__ void unpackf2(float& lo, float& hi, ull v) {
    unsigned a, b; asm("mov.b64 {%0, %1}, %2;" : "=r"(a), "=r"(b) : "l"(v));
    lo = __uint_as_float(a); hi = __uint_as_float(b);
}
__device__ __forceinline__ ull fma2(ull a, ull b, ull c) {
    ull d; asm("fma.rn.f32x2 %0, %1, %2, %3;" : "=l"(d) : "l"(a), "l"(b), "l"(c));
    return d;
}
__device__ __forceinline__ ull mul2(ull a, ull b) {
    ull d; asm("mul.rn.f32x2 %0, %1, %2;" : "=l"(d) : "l"(a), "l"(b));
    return d;
}
__device__ __forceinline__ ull add2(ull a, ull b) {
    ull d; asm("add.rn.f32x2 %0, %1, %2;" : "=l"(d) : "l"(a), "l"(b));
    return d;
}

// ------------------ K1a: stage-1 GEMM, split-K, k-pair f32x2 ----------------
__global__ __launch_bounds__(128) void k1a_gemm(
    const float* __restrict__ x,      // (4096, 1024)
    const float* __restrict__ w1)     // (64, 1024)
{
    __shared__ __align__(16) float xs[64][68];
    __shared__ __align__(16) float ws[64][68];

    const int tid = threadIdx.x;
    const int tg = blockIdx.x & 63, ks = blockIdx.x >> 6;
    const int tokbase = tg * 64;
    const int kbase = ks * 128;
    const int ct = tid & 7, tt = tid >> 3;

    ull acc[4][8];
#pragma unroll
    for (int i = 0; i < 4; i++)
#pragma unroll
        for (int j = 0; j < 8; j++) acc[i][j] = 0ull;

#pragma unroll 1
    for (int kt = 0; kt < 2; kt++) {
        const int k0 = kbase + kt * 64;
#pragma unroll
        for (int r = 0; r < 8; r++) {
            int f = tid + r * 128;               // 1024 float4 = 64 rows x 16
            int row = f >> 4, c4 = f & 15;
            *(float4*)&xs[row][c4 * 4] =
                *(const float4*)&x[(size_t)(tokbase + row) * D_IN + k0 + c4 * 4];
        }
#pragma unroll
        for (int r = 0; r < 8; r++) {
            int f = tid + r * 128;
            int row = f >> 4, c4 = f & 15;
            *(float4*)&ws[row][c4 * 4] =
                *(const float4*)&w1[(size_t)row * D_IN + k0 + c4 * 4];
        }
        __syncthreads();

#pragma unroll 8
        for (int kp = 0; kp < 32; kp++) {
            ull xv[4], wv[8];
#pragma unroll
            for (int i = 0; i < 4; i++) xv[i] = *(const ull*)&xs[tt + 16 * i][2 * kp];
#pragma unroll
            for (int j = 0; j < 8; j++) wv[j] = *(const ull*)&ws[ct + 8 * j][2 * kp];
#pragma unroll
            for (int i = 0; i < 4; i++)
#pragma unroll
                for (int j = 0; j < 8; j++)
                    acc[i][j] = fma2(xv[i], wv[j], acc[i][j]);
        }
        __syncthreads();
    }

#pragma unroll
    for (int i = 0; i < 4; i++)
#pragma unroll
        for (int j = 0; j < 8; j++) {
            float lo, hi; unpackf2(lo, hi, acc[i][j]);
            xs[tt + 16 * i][ct + 8 * j] = lo + hi;
        }
    __syncthreads();
#pragma unroll
    for (int r = 0; r < 8; r++) {
        int f = tid + r * 128;                   // 1024 f4 = 64 rows x 16
        int row = f >> 4, c4 = f & 15;
        *(float4*)&g_part[((size_t)ks * NTOK + tokbase + row) * 64 + c4 * 4] =
            *(float4*)&xs[row][c4 * 4];
    }
}

// ----------- K1b: combine partials -> delta GEMM + B/C epilogue -------------
__global__ __launch_bounds__(128) void k1b_delta(
    const float* __restrict__ dtw,    // (1024, 32)
    const float* __restrict__ bias,   // (1024)
    const float* __restrict__ gs,     // (B, L)
    const float* __restrict__ gcw,    // (16)
    const float* __restrict__ gcb,    // (16)
    const float* __restrict__ gCw)    // scalar
{
    __shared__ __align__(16) float xd[32][36];
    __shared__ __align__(16) float dw[128][34];   // stride 34: 2-way max on LDS.64

    const int tid = threadIdx.x;
    const int dg = blockIdx.x & 7, tg = blockIdx.x >> 3;
    const int tokbase = tg * 32;

#pragma unroll
    for (int r = 0; r < 2; r++) {
        int f = tid + r * 128;                   // 256 f4 = 32 rows x 8
        int row = f >> 3, c4 = f & 7;
        float4 s = make_float4(0.f, 0.f, 0.f, 0.f);
#pragma unroll
        for (int k = 0; k < KSPLIT; k++) {
            float4 v = *(const float4*)&g_part[((size_t)k * NTOK + tokbase + row) * 64 + c4 * 4];
            s.x += v.x; s.y += v.y; s.z += v.z; s.w += v.w;
        }
        *(float4*)&xd[row][c4 * 4] = s;
    }
#pragma unroll
    for (int r = 0; r < 16; r++) {
        int f = tid + r * 128;                   // 2048 float2 = 128 rows x 16
        int row = f >> 4, c2 = f & 15;
        *(float2*)&dw[row][c2 * 2] =
            *(const float2*)&dtw[(size_t)(dg * 128 + row) * 32 + c2 * 2];
    }
    if (dg == 0) {
        const float gCwv = gCw[0];
#pragma unroll
        for (int r = 0; r < 8; r++) {
            int f = tid + r * 128;               // 1024 = 32 tok x 32 n
            int t = f >> 5, n = f & 31;
            float s = 0.f;
#pragma unroll
            for (int k = 0; k < KSPLIT; k++)
                s += g_part[((size_t)k * NTOK + tokbase + t) * 64 + 32 + n];
            int tok = tokbase + t;
            int b = tok >> 11, l = tok & 2047;
            if (n >= 16) {
                int m = n - 16;
                s += gCwv * (gs[b * 2048 + m * 128 + (l >> 4)] * gcw[l & 15] + gcb[l & 15]);
            }
            g_bc[(size_t)tok * 32 + n] = s;
        }
    }
    __syncthreads();

    ull w2r[16];
    const ull* wrow = (const ull*)&dw[tid][0];
#pragma unroll
    for (int k = 0; k < 16; k++) w2r[k] = wrow[k];
    const int d = dg * 128 + tid;
    const float bz = bias[d];

#pragma unroll 4
    for (int t = 0; t < 32; t++) {
        const ulonglong2* xrow = (const ulonglong2*)&xd[t][0];   // broadcast
        ull a2 = 0ull, b2 = 0ull;
#pragma unroll
        for (int k = 0; k < 8; k++) {
            ulonglong2 qv = xrow[k];
            a2 = fma2(w2r[2 * k],     qv.x, a2);
            b2 = fma2(w2r[2 * k + 1], qv.y, b2);
        }
        float lo, hi; unpackf2(lo, hi, add2(a2, b2));
        g_delta[(size_t)(tokbase + t) * D_IN + d] = softplusf(lo + hi + bz);
    }
}

// --------------------- K2: scan phase 1 (chunk summaries) ------------------
__global__ __launch_bounds__(128) void k2_phase1(
    const float* __restrict__ x, const float* __restrict__ alogs)
{
    __shared__ __align__(16) float sB[CLEN][16];
    const int tid = threadIdx.x;
    const int bid = blockIdx.x;
    const int ch = bid & (NCHUNK - 1);
    const int dg = (bid >> 6) & 7;
    const int b  = bid >> 9;
    const int d  = dg * 128 + tid;
    const int l0 = ch * CLEN;

    {
        int s = tid >> 2, qd = tid & 3;
        ((float4*)&sB[s][0])[qd] = *(const float4*)&g_bc[(size_t)(b * 2048 + l0 + s) * 32 + qd * 4];
    }
    __syncthreads();

    float cn[16];
#pragma unroll
    for (int n = 0; n < 16; n++)
        cn[n] = -__expf(alogs[(size_t)d * 16 + n]) * LOG2E;
    bool fast = true;
#pragma unroll
    for (int n = 1; n < 16; n++) {
        float want = (float)(n + 1) * cn[0];
        fast = fast && (fabsf(cn[n] - want) <= 1e-4f * fabsf(want));
    }

    float sd = 0.f;
    const float* dlt = &g_delta[(size_t)(b * 2048 + l0) * D_IN + d];
    const float* xp  = &x[(size_t)(b * 2048 + l0) * D_IN + d];
    const size_t base = (size_t)(b * 1024 + d) * NCHUNK + ch;

    if (fast) {
        const float c0 = cn[0];
        ull h2[8];
#pragma unroll
        for (int k = 0; k < 8; k++) h2[k] = 0ull;
        float dv = dlt[0], xv = xp[0];
#pragma unroll 2
        for (int s = 0; s < CLEN; s++) {
            float dvn = 0.f, xvn = 0.f;
            if (s + 1 < CLEN) { dvn = dlt[(size_t)(s+1) * D_IN]; xvn = xp[(size_t)(s+1) * D_IN]; }
            sd += dv;
            float e  = ex2f(dv * c0);
            float e2 = e * e;
            float u  = dv * xv;
            ull uu = packf2(u, u);
            ull dd = packf2(e2, e2);
            ull P0 = packf2(e, e2);
            ull D4 = mul2(dd, dd);
            ull P1 = mul2(P0, dd);
            ull D8 = mul2(D4, D4);
            ull P2 = mul2(P0, D4);
            ull P3 = mul2(P1, D4);
            ull P4 = mul2(P0, D8);
            ull P5 = mul2(P1, D8);
            ull P6 = mul2(P2, D8);
            ull P7 = mul2(P3, D8);
            const ulonglong2* B2 = (const ulonglong2*)&sB[s][0];
            ulonglong2 b0 = B2[0], b1 = B2[1], b2v = B2[2], b3 = B2[3];
            h2[0] = fma2(P0, h2[0], mul2(uu, b0.x));
            h2[1] = fma2(P1, h2[1], mul2(uu, b0.y));
            h2[2] = fma2(P2, h2[2], mul2(uu, b1.x));
            h2[3] = fma2(P3, h2[3], mul2(uu, b1.y));
            h2[4] = fma2(P4, h2[4], mul2(uu, b2v.x));
            h2[5] = fma2(P5, h2[5], mul2(uu, b2v.y));
            h2[6] = fma2(P6, h2[6], mul2(uu, b3.x));
            h2[7] = fma2(P7, h2[7], mul2(uu, b3.y));
            dv = dvn; xv = xvn;
        }
        g_sd[base] = sd;
#pragma unroll
        for (int k = 0; k < 8; k++) *(ull*)&g_hloc[base * 16 + 2 * k] = h2[k];
    } else {
        float h[16];
#pragma unroll
        for (int n = 0; n < 16; n++) h[n] = 0.f;
        for (int s = 0; s < CLEN; s++) {
            float dv = dlt[(size_t)s * D_IN];
            float xv = xp[(size_t)s * D_IN];
            sd += dv;
            float u = dv * xv;
#pragma unroll
            for (int n = 0; n < 16; n++) {
                float a = ex2f(dv * cn[n]);
                h[n] = a * h[n] + u * sB[s][n];
            }
        }
        g_sd[base] = sd;
#pragma unroll
        for (int n = 0; n < 16; n++) g_hloc[base * 16 + n] = h[n];
    }
}

// ------------- K3: hierarchical combine (seg fold / scan / replay) ----------
// 2048 blocks = (b,d). 128 threads = (n:16, seg:8). Serial depth 8+8+8.
__global__ __launch_bounds__(128) void k3_combine(const float* __restrict__ alogs)
{
    __shared__ float ssd  [NSEG];              // segment delta-sums
    __shared__ float sHseg[NSEG][16];          // segment local end states
    __shared__ float sCar [NSEG][16];          // segment carry-ins

    const int tid = threadIdx.x;
    const int n = tid & 15;
    const int seg = tid >> 4;
    const int bd = blockIdx.x;                 // b*1024 + d
    const int d = bd & 1023;
    const float cnf = -__expf(alogs[(size_t)d * 16 + n]) * LOG2E;
    const size_t base = (size_t)bd * NCHUNK + seg * SEGLEN;

    // phase 1: load segment data, fold
    float sd[SEGLEN], hl[SEGLEN];
#pragma unroll
    for (int j = 0; j < SEGLEN; j++) {
        sd[j] = g_sd[base + j];
        hl[j] = g_hloc[(base + j) * 16 + n];
    }
    float H = 0.f, S = 0.f;
#pragma unroll
    for (int j = 0; j < SEGLEN; j++) {
        H = ex2f(sd[j] * cnf) * H + hl[j];
        S += sd[j];
    }
    sHseg[seg][n] = H;
    if (n == 0) ssd[seg] = S;
    __syncthreads();

    // phase 2: 16 threads scan the 8 segment summaries
    if (tid < 16) {
        float Hc = 0.f;
#pragma unroll
        for (int s = 0; s < NSEG; s++) {
            sCar[s][tid] = Hc;
            Hc = ex2f(ssd[s] * cnf) * Hc + sHseg[s][tid];
        }
    }
    __syncthreads();

    // phase 3: replay segment, writing carry-ins
    H = sCar[seg][n];
#pragma unroll
    for (int j = 0; j < SEGLEN; j++) {
        g_hin[(base + j) * 16 + n] = H;
        H = ex2f(sd[j] * cnf) * H + hl[j];
    }
}

// ----------------------- K4: scan phase 3 (emit y) --------------------------
__global__ __launch_bounds__(128) void k4_phase3(
    const float* __restrict__ x, const float* __restrict__ alogs,
    const float* __restrict__ Ds, float* __restrict__ y)
{
    __shared__ __align__(16) float sB[CLEN][16];
    __shared__ __align__(16) float sC[CLEN][16];
    const int tid = threadIdx.x;
    const int bid = blockIdx.x;
    const int ch = bid & (NCHUNK - 1);
    const int dg = (bid >> 6) & 7;
    const int b  = bid >> 9;
    const int d  = dg * 128 + tid;
    const int l0 = ch * CLEN;

#pragma unroll
    for (int i = 0; i < 2; i++) {
        int idx = tid + i * 128;
        int s = idx >> 3, qd = idx & 7;
        float4 v = *(const float4*)&g_bc[(size_t)(b * 2048 + l0 + s) * 32 + qd * 4];
        if (qd < 4) ((float4*)&sB[s][0])[qd] = v;
        else        ((float4*)&sC[s][0])[qd - 4] = v;
    }
    __syncthreads();

    float cn[16];
#pragma unroll
    for (int n = 0; n < 16; n++)
        cn[n] = -__expf(alogs[(size_t)d * 16 + n]) * LOG2E;
    bool fast = true;
#pragma unroll
    for (int n = 1; n < 16; n++) {
        float want = (float)(n + 1) * cn[0];
        fast = fast && (fabsf(cn[n] - want) <= 1e-4f * fabsf(want));
    }

    const size_t base = (size_t)(b * 1024 + d) * NCHUNK + ch;
    const float dsv = Ds[d];
    const float* dlt = &g_delta[(size_t)(b * 2048 + l0) * D_IN + d];
    const float* xp  = &x[(size_t)(b * 2048 + l0) * D_IN + d];
    float* yp        = &y[(size_t)(b * 2048 + l0) * D_IN + d];

    if (fast) {
        const float c0 = cn[0];
        ull h2[8];
#pragma unroll
        for (int k = 0; k < 8; k++) h2[k] = *(const ull*)&g_hin[base * 16 + 2 * k];
        float dv = dlt[0], xv = xp[0];
#pragma unroll 2
        for (int s = 0; s < CLEN; s++) {
            float dvn = 0.f, xvn = 0.f;
            if (s + 1 < CLEN) { dvn = dlt[(size_t)(s+1) * D_IN]; xvn = xp[(size_t)(s+1) * D_IN]; }
            float e  = ex2f(dv * c0);
            float e2 = e * e;
            float u  = dv * xv;
            ull uu = packf2(u, u);
            ull dd = packf2(e2, e2);
            ull P0 = packf2(e, e2);
            ull D4 = mul2(dd, dd);
            ull P1 = mul2(P0, dd);
            ull D8 = mul2(D4, D4);
            ull P2 = mul2(P0, D4);
            ull P3 = mul2(P1, D4);
            ull P4 = mul2(P0, D8);
            ull P5 = mul2(P1, D8);
            ull P6 = mul2(P2, D8);
            ull P7 = mul2(P3, D8);
            const ulonglong2* B2 = (const ulonglong2*)&sB[s][0];
            const ulonglong2* C2 = (const ulonglong2*)&sC[s][0];
            ulonglong2 b0 = B2[0], b1 = B2[1], b2v = B2[2], b3 = B2[3];
            ulonglong2 cc0 = C2[0], cc1 = C2[1], cc2 = C2[2], cc3 = C2[3];
            ull y2a, y2b;
            h2[0] = fma2(P0, h2[0], mul2(uu, b0.x));  y2a = mul2(h2[0], cc0.x);
            h2[1] = fma2(P1, h2[1], mul2(uu, b0.y));  y2b = mul2(h2[1], cc0.y);
            h2[2] = fma2(P2, h2[2], mul2(uu, b1.x));  y2a = fma2(h2[2], cc1.x, y2a);
            h2[3] = fma2(P3, h2[3], mul2(uu, b1.y));  y2b = fma2(h2[3], cc1.y, y2b);
            h2[4] = fma2(P4, h2[4], mul2(uu, b2v.x)); y2a = fma2(h2[4], cc2.x, y2a);
            h2[5] = fma2(P5, h2[5], mul2(uu, b2v.y)); y2b = fma2(h2[5], cc2.y, y2b);
            h2[6] = fma2(P6, h2[6], mul2(uu, b3.x));  y2a = fma2(h2[6], cc3.x, y2a);
            h2[7] = fma2(P7, h2[7], mul2(uu, b3.y));  y2b = fma2(h2[7], cc3.y, y2b);
            float ylo, yhi; unpackf2(ylo, yhi, add2(y2a, y2b));
            yp[(size_t)s * D_IN] = ylo + yhi + xv * dsv;
            dv = dvn; xv = xvn;
        }
    } else {
        float h[16];
#pragma unroll
        for (int n = 0; n < 16; n++) h[n] = g_hin[base * 16 + n];
        for (int s = 0; s < CLEN; s++) {
            float dv = dlt[(size_t)s * D_IN];
            float xv = xp[(size_t)s * D_IN];
            float u = dv * xv;
            float y0 = 0.f, y1 = 0.f;
#pragma unroll
            for (int n = 0; n < 16; n++) {
                float a = ex2f(dv * cn[n]);
                h[n] = a * h[n] + u * sB[s][n];
                if (n & 1) y1 += h[n] * sC[s][n];
                else       y0 += h[n] * sC[s][n];
            }
            yp[(size_t)s * D_IN] = y0 + y1 + xv * dsv;
        }
    }
}

// ------------------------------- launcher ----------------------------------
extern "C" void kernel_launch(void* const* d_in, const int* in_sizes, int n_in,
                              void* d_out, int out_size)
{
    const float* x     = (const float*)d_in[0];
    const float* gs    = (const float*)d_in[1];
    const float* w1    = (const float*)d_in[2];
    const float* dtw   = (const float*)d_in[3];
    const float* bias  = (const float*)d_in[4];
    const float* alogs = (const float*)d_in[5];
    const float* Ds    = (const float*)d_in[6];
    const float* gcw   = (const float*)d_in[7];
    const float* gcb   = (const float*)d_in[8];
    const float* gCw   = (const float*)d_in[9];
    float* y = (float*)d_out;

    k1a_gemm <<<64 * KSPLIT, 128>>>(x, w1);
    k1b_delta<<<128 * 8, 128>>>(dtw, bias, gs, gcw, gcb, gCw);
    k2_phase1<<<BATCH * 8 * NCHUNK, 128>>>(x, alogs);
    k3_combine<<<BATCH * D_IN, 128>>>(alogs);
    k4_phase3<<<BATCH * 8 * NCHUNK, 128>>>(x, alogs, Ds, y);
}

// round 7
// speedup vs baseline: 1.9409x; 1.0193x over previous
#include <cuda_runtime.h>
#include <math.h>

#define L_SEQ   2048
#define D_IN    1024
#define N_ST    16
#define BATCH   2
#define NTOK    (BATCH * L_SEQ)      // 4096
#define NCHUNK  64
#define CLEN    32                   // L_SEQ / NCHUNK
#define NSEG    8
#define SEGLEN  8                    // NCHUNK / NSEG
#define KSPLIT  8
#define LOG2E   1.4426950408889634f

typedef unsigned long long ull;

// ------------------------------- scratch ----------------------------------
__device__ float g_part [KSPLIT * NTOK * 64];              // split-K partials
__device__ float g_delta[NTOK * D_IN];                     // (tok, d)
__device__ float g_bc   [NTOK * 32];                       // (tok, n)  n<16:B, n>=16:C
__device__ float g_sd   [BATCH * D_IN * NCHUNK];
__device__ float g_hloc [BATCH * D_IN * NCHUNK * N_ST];
__device__ float g_hin  [BATCH * D_IN * NCHUNK * N_ST];

__device__ __forceinline__ float ex2f(float x) {
    float r; asm("ex2.approx.ftz.f32 %0, %1;" : "=f"(r) : "f"(x)); return r;
}
__device__ __forceinline__ float softplusf(float z) {
    return fmaxf(z, 0.0f) + log1pf(__expf(-fabsf(z)));
}
__device__ __forceinline__ ull packf2(float lo, float hi) {
    ull d; asm("mov.b64 %0, {%1, %2};" : "=l"(d) : "r"(__float_as_uint(lo)), "r"(__float_as_uint(hi)));
    return d;
}
__device__ __forceinline__ void unpackf2(float& lo, float& hi, ull v) {
    unsigned a, b; asm("mov.b64 {%0, %1}, %2;" : "=r"(a), "=r"(b) : "l"(v));
    lo = __uint_as_float(a); hi = __uint_as_float(b);
}
__device__ __forceinline__ ull fma2(ull a, ull b, ull c) {
    ull d; asm("fma.rn.f32x2 %0, %1, %2, %3;" : "=l"(d) : "l"(a), "l"(b), "l"(c));
    return d;
}
__device__ __forceinline__ ull mul2(ull a, ull b) {
    ull d; asm("mul.rn.f32x2 %0, %1, %2;" : "=l"(d) : "l"(a), "l"(b));
    return d;
}
__device__ __forceinline__ ull add2(ull a, ull b) {
    ull d; asm("add.rn.f32x2 %0, %1, %2;" : "=l"(d) : "l"(a), "l"(b));
    return d;
}

// ------------------ K1a: stage-1 GEMM, split-K, k-pair f32x2 ----------------
__global__ __launch_bounds__(128) void k1a_gemm(
    const float* __restrict__ x,      // (4096, 1024)
    const float* __restrict__ w1)     // (64, 1024)
{
    __shared__ __align__(16) float xs[64][68];
    __shared__ __align__(16) float ws[64][68];

    const int tid = threadIdx.x;
    const int tg = blockIdx.x & 63, ks = blockIdx.x >> 6;
    const int tokbase = tg * 64;
    const int kbase = ks * 128;
    const int ct = tid & 7, tt = tid >> 3;

    ull acc[4][8];
#pragma unroll
    for (int i = 0; i < 4; i++)
#pragma unroll
        for (int j = 0; j < 8; j++) acc[i][j] = 0ull;

#pragma unroll 1
    for (int kt = 0; kt < 2; kt++) {
        const int k0 = kbase + kt * 64;
#pragma unroll
        for (int r = 0; r < 8; r++) {
            int f = tid + r * 128;               // 1024 float4 = 64 rows x 16
            int row = f >> 4, c4 = f & 15;
            *(float4*)&xs[row][c4 * 4] =
                *(const float4*)&x[(size_t)(tokbase + row) * D_IN + k0 + c4 * 4];
        }
#pragma unroll
        for (int r = 0; r < 8; r++) {
            int f = tid + r * 128;
            int row = f >> 4, c4 = f & 15;
            *(float4*)&ws[row][c4 * 4] =
                *(const float4*)&w1[(size_t)row * D_IN + k0 + c4 * 4];
        }
        __syncthreads();

#pragma unroll 8
        for (int kp = 0; kp < 32; kp++) {
            ull xv[4], wv[8];
#pragma unroll
            for (int i = 0; i < 4; i++) xv[i] = *(const ull*)&xs[tt + 16 * i][2 * kp];
#pragma unroll
            for (int j = 0; j < 8; j++) wv[j] = *(const ull*)&ws[ct + 8 * j][2 * kp];
#pragma unroll
            for (int i = 0; i < 4; i++)
#pragma unroll
                for (int j = 0; j < 8; j++)
                    acc[i][j] = fma2(xv[i], wv[j], acc[i][j]);
        }
        __syncthreads();
    }

#pragma unroll
    for (int i = 0; i < 4; i++)
#pragma unroll
        for (int j = 0; j < 8; j++) {
            float lo, hi; unpackf2(lo, hi, acc[i][j]);
            xs[tt + 16 * i][ct + 8 * j] = lo + hi;
        }
    __syncthreads();
#pragma unroll
    for (int r = 0; r < 8; r++) {
        int f = tid + r * 128;                   // 1024 f4 = 64 rows x 16
        int row = f >> 4, c4 = f & 15;
        *(float4*)&g_part[((size_t)ks * NTOK + tokbase + row) * 64 + c4 * 4] =
            *(float4*)&xs[row][c4 * 4];
    }
}

// ----------- K1b: combine partials -> delta GEMM + B/C epilogue -------------
__global__ __launch_bounds__(128) void k1b_delta(
    const float* __restrict__ dtw,    // (1024, 32)
    const float* __restrict__ bias,   // (1024)
    const float* __restrict__ gs,     // (B, L)
    const float* __restrict__ gcw,    // (16)
    const float* __restrict__ gcb,    // (16)
    const float* __restrict__ gCw)    // scalar
{
    __shared__ __align__(16) float xd[32][36];
    __shared__ __align__(16) float dw[128][34];   // stride 34: 2-way max on LDS.64

    const int tid = threadIdx.x;
    const int dg = blockIdx.x & 7, tg = blockIdx.x >> 3;
    const int tokbase = tg * 32;

#pragma unroll
    for (int r = 0; r < 2; r++) {
        int f = tid + r * 128;                   // 256 f4 = 32 rows x 8
        int row = f >> 3, c4 = f & 7;
        float4 s = make_float4(0.f, 0.f, 0.f, 0.f);
#pragma unroll
        for (int k = 0; k < KSPLIT; k++) {
            float4 v = *(const float4*)&g_part[((size_t)k * NTOK + tokbase + row) * 64 + c4 * 4];
            s.x += v.x; s.y += v.y; s.z += v.z; s.w += v.w;
        }
        *(float4*)&xd[row][c4 * 4] = s;
    }
#pragma unroll
    for (int r = 0; r < 16; r++) {
        int f = tid + r * 128;                   // 2048 float2 = 128 rows x 16
        int row = f >> 4, c2 = f & 15;
        *(float2*)&dw[row][c2 * 2] =
            *(const float2*)&dtw[(size_t)(dg * 128 + row) * 32 + c2 * 2];
    }
    if (dg == 0) {
        const float gCwv = gCw[0];
#pragma unroll
        for (int r = 0; r < 8; r++) {
            int f = tid + r * 128;               // 1024 = 32 tok x 32 n
            int t = f >> 5, n = f & 31;
            float s = 0.f;
#pragma unroll
            for (int k = 0; k < KSPLIT; k++)
                s += g_part[((size_t)k * NTOK + tokbase + t) * 64 + 32 + n];
            int tok = tokbase + t;
            int b = tok >> 11, l = tok & 2047;
            if (n >= 16) {
                int m = n - 16;
                s += gCwv * (gs[b * 2048 + m * 128 + (l >> 4)] * gcw[l & 15] + gcb[l & 15]);
            }
            g_bc[(size_t)tok * 32 + n] = s;
        }
    }
    __syncthreads();

    ull w2r[16];
    const ull* wrow = (const ull*)&dw[tid][0];
#pragma unroll
    for (int k = 0; k < 16; k++) w2r[k] = wrow[k];
    const int d = dg * 128 + tid;
    const float bz = bias[d];

#pragma unroll 4
    for (int t = 0; t < 32; t++) {
        const ulonglong2* xrow = (const ulonglong2*)&xd[t][0];   // broadcast
        ull a2 = 0ull, b2 = 0ull;
#pragma unroll
        for (int k = 0; k < 8; k++) {
            ulonglong2 qv = xrow[k];
            a2 = fma2(w2r[2 * k],     qv.x, a2);
            b2 = fma2(w2r[2 * k + 1], qv.y, b2);
        }
        float lo, hi; unpackf2(lo, hi, add2(a2, b2));
        g_delta[(size_t)(tokbase + t) * D_IN + d] = softplusf(lo + hi + bz);
    }
}

// --------------------- K2: scan phase 1 (chunk summaries) ------------------
// smem-prefetched delta/x: batched LDG->STS (MLP=64), no barrier after
// (own-column data; same-thread STS->LDS is scoreboard-ordered).
__global__ __launch_bounds__(128) void k2_phase1(
    const float* __restrict__ x, const float* __restrict__ alogs)
{
    __shared__ __align__(16) float sB[CLEN][16];
    __shared__ float sD[CLEN][128];
    __shared__ float sX[CLEN][128];
    const int tid = threadIdx.x;
    const int bid = blockIdx.x;
    const int ch = bid & (NCHUNK - 1);
    const int dg = (bid >> 6) & 7;
    const int b  = bid >> 9;
    const int d  = dg * 128 + tid;
    const int l0 = ch * CLEN;

    {
        int s = tid >> 2, qd = tid & 3;
        ((float4*)&sB[s][0])[qd] = *(const float4*)&g_bc[(size_t)(b * 2048 + l0 + s) * 32 + qd * 4];
    }
    __syncthreads();     // protects sB only; placed BEFORE the big prefetch

    const float* dlt = &g_delta[(size_t)(b * 2048 + l0) * D_IN + d];
    const float* xp  = &x[(size_t)(b * 2048 + l0) * D_IN + d];
#pragma unroll
    for (int s = 0; s < CLEN; s++) {
        sD[s][tid] = dlt[(size_t)s * D_IN];
        sX[s][tid] = xp[(size_t)s * D_IN];
    }

    float cn[16];
#pragma unroll
    for (int n = 0; n < 16; n++)
        cn[n] = -__expf(alogs[(size_t)d * 16 + n]) * LOG2E;
    bool fast = true;
#pragma unroll
    for (int n = 1; n < 16; n++) {
        float want = (float)(n + 1) * cn[0];
        fast = fast && (fabsf(cn[n] - want) <= 1e-4f * fabsf(want));
    }

    float sd = 0.f;
    const size_t base = (size_t)(b * 1024 + d) * NCHUNK + ch;

    if (fast) {
        const float c0 = cn[0];
        ull h2[8];
#pragma unroll
        for (int k = 0; k < 8; k++) h2[k] = 0ull;
#pragma unroll 4
        for (int s = 0; s < CLEN; s++) {
            float dv = sD[s][tid];
            float xv = sX[s][tid];
            sd += dv;
            float e  = ex2f(dv * c0);
            float e2 = e * e;
            float u  = dv * xv;
            ull uu = packf2(u, u);
            ull dd = packf2(e2, e2);
            ull P0 = packf2(e, e2);
            ull D4 = mul2(dd, dd);
            ull P1 = mul2(P0, dd);
            ull D8 = mul2(D4, D4);
            ull P2 = mul2(P0, D4);
            ull P3 = mul2(P1, D4);
            ull P4 = mul2(P0, D8);
            ull P5 = mul2(P1, D8);
            ull P6 = mul2(P2, D8);
            ull P7 = mul2(P3, D8);
            const ulonglong2* B2 = (const ulonglong2*)&sB[s][0];
            ulonglong2 b0 = B2[0], b1 = B2[1], b2v = B2[2], b3 = B2[3];
            h2[0] = fma2(P0, h2[0], mul2(uu, b0.x));
            h2[1] = fma2(P1, h2[1], mul2(uu, b0.y));
            h2[2] = fma2(P2, h2[2], mul2(uu, b1.x));
            h2[3] = fma2(P3, h2[3], mul2(uu, b1.y));
            h2[4] = fma2(P4, h2[4], mul2(uu, b2v.x));
            h2[5] = fma2(P5, h2[5], mul2(uu, b2v.y));
            h2[6] = fma2(P6, h2[6], mul2(uu, b3.x));
            h2[7] = fma2(P7, h2[7], mul2(uu, b3.y));
        }
        g_sd[base] = sd;
#pragma unroll
        for (int k = 0; k < 8; k++) *(ull*)&g_hloc[base * 16 + 2 * k] = h2[k];
    } else {
        float h[16];
#pragma unroll
        for (int n = 0; n < 16; n++) h[n] = 0.f;
        for (int s = 0; s < CLEN; s++) {
            float dv = sD[s][tid];
            float xv = sX[s][tid];
            sd += dv;
            float u = dv * xv;
#pragma unroll
            for (int n = 0; n < 16; n++) {
                float a = ex2f(dv * cn[n]);
                h[n] = a * h[n] + u * sB[s][n];
            }
        }
        g_sd[base] = sd;
#pragma unroll
        for (int n = 0; n < 16; n++) g_hloc[base * 16 + n] = h[n];
    }
}

// ------------- K3: hierarchical combine (seg fold / scan / replay) ----------
__global__ __launch_bounds__(128) void k3_combine(const float* __restrict__ alogs)
{
    __shared__ float ssd  [NSEG];
    __shared__ float sHseg[NSEG][16];
    __shared__ float sCar [NSEG][16];

    const int tid = threadIdx.x;
    const int n = tid & 15;
    const int seg = tid >> 4;
    const int bd = blockIdx.x;                 // b*1024 + d
    const int d = bd & 1023;
    const float cnf = -__expf(alogs[(size_t)d * 16 + n]) * LOG2E;
    const size_t base = (size_t)bd * NCHUNK + seg * SEGLEN;

    float sd[SEGLEN], hl[SEGLEN];
#pragma unroll
    for (int j = 0; j < SEGLEN; j++) {
        sd[j] = g_sd[base + j];
        hl[j] = g_hloc[(base + j) * 16 + n];
    }
    float H = 0.f, S = 0.f;
#pragma unroll
    for (int j = 0; j < SEGLEN; j++) {
        H = ex2f(sd[j] * cnf) * H + hl[j];
        S += sd[j];
    }
    sHseg[seg][n] = H;
    if (n == 0) ssd[seg] = S;
    __syncthreads();

    if (tid < 16) {
        float Hc = 0.f;
#pragma unroll
        for (int s = 0; s < NSEG; s++) {
            sCar[s][tid] = Hc;
            Hc = ex2f(ssd[s] * cnf) * Hc + sHseg[s][tid];
        }
    }
    __syncthreads();

    H = sCar[seg][n];
#pragma unroll
    for (int j = 0; j < SEGLEN; j++) {
        g_hin[(base + j) * 16 + n] = H;
        H = ex2f(sd[j] * cnf) * H + hl[j];
    }
}

// ----------------------- K4: scan phase 3 (emit y) --------------------------
__global__ __launch_bounds__(128) void k4_phase3(
    const float* __restrict__ x, const float* __restrict__ alogs,
    const float* __restrict__ Ds, float* __restrict__ y)
{
    __shared__ __align__(16) float sB[CLEN][16];
    __shared__ __align__(16) float sC[CLEN][16];
    __shared__ float sD[CLEN][128];
    __shared__ float sX[CLEN][128];
    const int tid = threadIdx.x;
    const int bid = blockIdx.x;
    const int ch = bid & (NCHUNK - 1);
    const int dg = (bid >> 6) & 7;
    const int b  = bid >> 9;
    const int d  = dg * 128 + tid;
    const int l0 = ch * CLEN;

#pragma unroll
    for (int i = 0; i < 2; i++) {
        int idx = tid + i * 128;
        int s = idx >> 3, qd = idx & 7;
        float4 v = *(const float4*)&g_bc[(size_t)(b * 2048 + l0 + s) * 32 + qd * 4];
        if (qd < 4) ((float4*)&sB[s][0])[qd] = v;
        else        ((float4*)&sC[s][0])[qd - 4] = v;
    }
    __syncthreads();     // protects sB/sC only; before the prefetch

    const size_t base = (size_t)(b * 1024 + d) * NCHUNK + ch;
    ull h2[8];
#pragma unroll
    for (int k = 0; k < 8; k++) h2[k] = *(const ull*)&g_hin[base * 16 + 2 * k];

    const float* dlt = &g_delta[(size_t)(b * 2048 + l0) * D_IN + d];
    const float* xp  = &x[(size_t)(b * 2048 + l0) * D_IN + d];
#pragma unroll
    for (int s = 0; s < CLEN; s++) {
        sD[s][tid] = dlt[(size_t)s * D_IN];
        sX[s][tid] = xp[(size_t)s * D_IN];
    }

    float cn[16];
#pragma unroll
    for (int n = 0; n < 16; n++)
        cn[n] = -__expf(alogs[(size_t)d * 16 + n]) * LOG2E;
    bool fast = true;
#pragma unroll
    for (int n = 1; n < 16; n++) {
        float want = (float)(n + 1) * cn[0];
        fast = fast && (fabsf(cn[n] - want) <= 1e-4f * fabsf(want));
    }

    const float dsv = Ds[d];
    float* yp = &y[(size_t)(b * 2048 + l0) * D_IN + d];

    if (fast) {
        const float c0 = cn[0];
#pragma unroll 4
        for (int s = 0; s < CLEN; s++) {
            float dv = sD[s][tid];
            float xv = sX[s][tid];
            float e  = ex2f(dv * c0);
            float e2 = e * e;
            float u  = dv * xv;
            ull uu = packf2(u, u);
            ull dd = packf2(e2, e2);
            ull P0 = packf2(e, e2);
            ull D4 = mul2(dd, dd);
            ull P1 = mul2(P0, dd);
            ull D8 = mul2(D4, D4);
            ull P2 = mul2(P0, D4);
            ull P3 = mul2(P1, D4);
            ull P4 = mul2(P0, D8);
            ull P5 = mul2(P1, D8);
            ull P6 = mul2(P2, D8);
            ull P7 = mul2(P3, D8);
            const ulonglong2* B2 = (const ulonglong2*)&sB[s][0];
            const ulonglong2* C2 = (const ulonglong2*)&sC[s][0];
            ulonglong2 b0 = B2[0], b1 = B2[1], b2v = B2[2], b3 = B2[3];
            ulonglong2 cc0 = C2[0], cc1 = C2[1], cc2 = C2[2], cc3 = C2[3];
            ull y2a, y2b;
            h2[0] = fma2(P0, h2[0], mul2(uu, b0.x));  y2a = mul2(h2[0], cc0.x);
            h2[1] = fma2(P1, h2[1], mul2(uu, b0.y));  y2b = mul2(h2[1], cc0.y);
            h2[2] = fma2(P2, h2[2], mul2(uu, b1.x));  y2a = fma2(h2[2], cc1.x, y2a);
            h2[3] = fma2(P3, h2[3], mul2(uu, b1.y));  y2b = fma2(h2[3], cc1.y, y2b);
            h2[4] = fma2(P4, h2[4], mul2(uu, b2v.x)); y2a = fma2(h2[4], cc2.x, y2a);
            h2[5] = fma2(P5, h2[5], mul2(uu, b2v.y)); y2b = fma2(h2[5], cc2.y, y2b);
            h2[6] = fma2(P6, h2[6], mul2(uu, b3.x));  y2a = fma2(h2[6], cc3.x, y2a);
            h2[7] = fma2(P7, h2[7], mul2(uu, b3.y));  y2b = fma2(h2[7], cc3.y, y2b);
            float ylo, yhi; unpackf2(ylo, yhi, add2(y2a, y2b));
            yp[(size_t)s * D_IN] = ylo + yhi + xv * dsv;
        }
    } else {
        float h[16];
#pragma unroll
        for (int n = 0; n < 16; n++) { float lo, hi; unpackf2(lo, hi, h2[n >> 1]); h[n] = (n & 1) ? hi : lo; }
        for (int s = 0; s < CLEN; s++) {
            float dv = sD[s][tid];
            float xv = sX[s][tid];
            float u = dv * xv;
            float y0 = 0.f, y1 = 0.f;
#pragma unroll
            for (int n = 0; n < 16; n++) {
                float a = ex2f(dv * cn[n]);
                h[n] = a * h[n] + u * sB[s][n];
                if (n & 1) y1 += h[n] * sC[s][n];
                else       y0 += h[n] * sC[s][n];
            }
            yp[(size_t)s * D_IN] = y0 + y1 + xv * dsv;
        }
    }
}

// ------------------------------- launcher ----------------------------------
extern "C" void kernel_launch(void* const* d_in, const int* in_sizes, int n_in,
                              void* d_out, int out_size)
{
    const float* x     = (const float*)d_in[0];
    const float* gs    = (const float*)d_in[1];
    const float* w1    = (const float*)d_in[2];
    const float* dtw   = (const float*)d_in[3];
    const float* bias  = (const float*)d_in[4];
    const float* alogs = (const float*)d_in[5];
    const float* Ds    = (const float*)d_in[6];
    const float* gcw   = (const float*)d_in[7];
    const float* gcb   = (const float*)d_in[8];
    const float* gCw   = (const float*)d_in[9];
    float* y = (float*)d_out;

    k1a_gemm <<<64 * KSPLIT, 128>>>(x, w1);
    k1b_delta<<<128 * 8, 128>>>(dtw, bias, gs, gcw, gcb, gCw);
    k2_phase1<<<BATCH * 8 * NCHUNK, 128>>>(x, alogs);
    k3_combine<<<BATCH * D_IN, 128>>>(alogs);
    k4_phase3<<<BATCH * 8 * NCHUNK, 128>>>(x, alogs, Ds, y);
}

// round 8
// speedup vs baseline: 1.9930x; 1.0268x over previous
#include <cuda_runtime.h>
#include <math.h>

#define L_SEQ   2048
#define D_IN    1024
#define N_ST    16
#define BATCH   2
#define NTOK    (BATCH * L_SEQ)      // 4096
#define NCHUNK  64
#define CLEN    32                   // L_SEQ / NCHUNK
#define NSEG    8
#define SEGLEN  8                    // NCHUNK / NSEG
#define KSPLIT  8
#define LOG2E   1.4426950408889634f

typedef unsigned long long ull;

// ------------------------------- scratch ----------------------------------
__device__ float g_part [KSPLIT * NTOK * 64];              // split-K partials
__device__ float g_delta[NTOK * D_IN];                     // (tok, d)
__device__ float g_bc   [NTOK * 32];                       // (tok, n)  n<16:B, n>=16:C
__device__ float g_sd   [BATCH * D_IN * NCHUNK];
__device__ float g_hloc [BATCH * D_IN * NCHUNK * N_ST];
__device__ float g_hin  [BATCH * D_IN * NCHUNK * N_ST];

__device__ __forceinline__ float ex2f(float x) {
    float r; asm("ex2.approx.ftz.f32 %0, %1;" : "=f"(r) : "f"(x)); return r;
}
__device__ __forceinline__ float softplusf(float z) {
    return fmaxf(z, 0.0f) + log1pf(__expf(-fabsf(z)));
}
__device__ __forceinline__ ull packf2(float lo, float hi) {
    ull d; asm("mov.b64 %0, {%1, %2};" : "=l"(d) : "r"(__float_as_uint(lo)), "r"(__float_as_uint(hi)));
    return d;
}
__device__ __forceinline__ void unpackf2(float& lo, float& hi, ull v) {
    unsigned a, b; asm("mov.b64 {%0, %1}, %2;" : "=r"(a), "=r"(b) : "l"(v));
    lo = __uint_as_float(a); hi = __uint_as_float(b);
}
__device__ __forceinline__ ull fma2(ull a, ull b, ull c) {
    ull d; asm("fma.rn.f32x2 %0, %1, %2, %3;" : "=l"(d) : "l"(a), "l"(b), "l"(c));
    return d;
}
__device__ __forceinline__ ull mul2(ull a, ull b) {
    ull d; asm("mul.rn.f32x2 %0, %1, %2;" : "=l"(d) : "l"(a), "l"(b));
    return d;
}
__device__ __forceinline__ ull add2(ull a, ull b) {
    ull d; asm("add.rn.f32x2 %0, %1, %2;" : "=l"(d) : "l"(a), "l"(b));
    return d;
}

// ------------------ K1a: stage-1 GEMM, split-K, k-pair f32x2 ----------------
__global__ __launch_bounds__(128) void k1a_gemm(
    const float* __restrict__ x,      // (4096, 1024)
    const float* __restrict__ w1)     // (64, 1024)
{
    __shared__ __align__(16) float xs[64][68];
    __shared__ __align__(16) float ws[64][68];

    const int tid = threadIdx.x;
    const int tg = blockIdx.x & 63, ks = blockIdx.x >> 6;
    const int tokbase = tg * 64;
    const int kbase = ks * 128;
    const int ct = tid & 7, tt = tid >> 3;

    ull acc[4][8];
#pragma unroll
    for (int i = 0; i < 4; i++)
#pragma unroll
        for (int j = 0; j < 8; j++) acc[i][j] = 0ull;

#pragma unroll 1
    for (int kt = 0; kt < 2; kt++) {
        const int k0 = kbase + kt * 64;
#pragma unroll
        for (int r = 0; r < 8; r++) {
            int f = tid + r * 128;               // 1024 float4 = 64 rows x 16
            int row = f >> 4, c4 = f & 15;
            *(float4*)&xs[row][c4 * 4] =
                *(const float4*)&x[(size_t)(tokbase + row) * D_IN + k0 + c4 * 4];
        }
#pragma unroll
        for (int r = 0; r < 8; r++) {
            int f = tid + r * 128;
            int row = f >> 4, c4 = f & 15;
            *(float4*)&ws[row][c4 * 4] =
                *(const float4*)&w1[(size_t)row * D_IN + k0 + c4 * 4];
        }
        __syncthreads();

#pragma unroll 8
        for (int kp = 0; kp < 32; kp++) {
            ull xv[4], wv[8];
#pragma unroll
            for (int i = 0; i < 4; i++) xv[i] = *(const ull*)&xs[tt + 16 * i][2 * kp];
#pragma unroll
            for (int j = 0; j < 8; j++) wv[j] = *(const ull*)&ws[ct + 8 * j][2 * kp];
#pragma unroll
            for (int i = 0; i < 4; i++)
#pragma unroll
                for (int j = 0; j < 8; j++)
                    acc[i][j] = fma2(xv[i], wv[j], acc[i][j]);
        }
        __syncthreads();
    }

#pragma unroll
    for (int i = 0; i < 4; i++)
#pragma unroll
        for (int j = 0; j < 8; j++) {
            float lo, hi; unpackf2(lo, hi, acc[i][j]);
            xs[tt + 16 * i][ct + 8 * j] = lo + hi;
        }
    __syncthreads();
#pragma unroll
    for (int r = 0; r < 8; r++) {
        int f = tid + r * 128;                   // 1024 f4 = 64 rows x 16
        int row = f >> 4, c4 = f & 15;
        *(float4*)&g_part[((size_t)ks * NTOK + tokbase + row) * 64 + c4 * 4] =
            *(float4*)&xs[row][c4 * 4];
    }
}

// --- K1b fused: partials -> delta GEMM + B/C epilogue + phase-1 chunk scan ---
// 1024 blocks = 128 token-groups(=chunks, 32 tok) x 8 d-groups(128 d).
__global__ __launch_bounds__(128) void k1b_fused(
    const float* __restrict__ x,      // (4096, 1024)
    const float* __restrict__ dtw,    // (1024, 32)
    const float* __restrict__ bias,   // (1024)
    const float* __restrict__ gs,     // (B, L)
    const float* __restrict__ gcw,    // (16)
    const float* __restrict__ gcb,    // (16)
    const float* __restrict__ gCw,    // scalar
    const float* __restrict__ alogs)  // (1024, 16)
{
    __shared__ __align__(16) float xd[32][36];
    __shared__ __align__(16) float dw[128][34];   // stride 34: 2-way max on LDS.64
    __shared__ __align__(16) float sB[CLEN][16];
    __shared__ float sX [CLEN][128];
    __shared__ float sDl[CLEN][128];

    const int tid = threadIdx.x;
    const int dg = blockIdx.x & 7, tg = blockIdx.x >> 3;
    const int tokbase = tg * 32;
    const int b  = tokbase >> 11;
    const int ch = (tokbase & 2047) >> 5;         // chunk index within batch
    const int d  = dg * 128 + tid;

    // ---- gather: split-K sums for dts_r, dtW tile, B tile, x prefetch ----
#pragma unroll
    for (int r = 0; r < 2; r++) {
        int f = tid + r * 128;                   // 256 f4 = 32 rows x 8
        int row = f >> 3, c4 = f & 7;
        float4 s = make_float4(0.f, 0.f, 0.f, 0.f);
#pragma unroll
        for (int k = 0; k < KSPLIT; k++) {
            float4 v = *(const float4*)&g_part[((size_t)k * NTOK + tokbase + row) * 64 + c4 * 4];
            s.x += v.x; s.y += v.y; s.z += v.z; s.w += v.w;
        }
        *(float4*)&xd[row][c4 * 4] = s;
    }
#pragma unroll
    for (int r = 0; r < 16; r++) {
        int f = tid + r * 128;                   // 2048 float2 = 128 rows x 16
        int row = f >> 4, c2 = f & 15;
        *(float2*)&dw[row][c2 * 2] =
            *(const float2*)&dtw[(size_t)(dg * 128 + row) * 32 + c2 * 2];
    }
    // B tile straight from partials (B needs no gradient correction)
#pragma unroll
    for (int i = 0; i < 4; i++) {
        int idx = tid + i * 128;                 // 512 = 32 s x 16 n
        int s = idx >> 4, n = idx & 15;
        float v = 0.f;
#pragma unroll
        for (int k = 0; k < KSPLIT; k++)
            v += g_part[((size_t)k * NTOK + tokbase + s) * 64 + 32 + n];
        sB[s][n] = v;
    }
    // x prefetch (own column)
    {
        const float* xp = &x[(size_t)tokbase * D_IN + d];
#pragma unroll
        for (int s = 0; s < CLEN; s++) sX[s][tid] = xp[(size_t)s * D_IN];
    }
    // dg==0 blocks emit B and corrected C to gmem (consumed by k4)
    if (dg == 0) {
        const float gCwv = gCw[0];
#pragma unroll
        for (int r = 0; r < 8; r++) {
            int f = tid + r * 128;               // 1024 = 32 tok x 32 n
            int t = f >> 5, n = f & 31;
            float s = 0.f;
#pragma unroll
            for (int k = 0; k < KSPLIT; k++)
                s += g_part[((size_t)k * NTOK + tokbase + t) * 64 + 32 + n];
            int tok = tokbase + t;
            int l = tok & 2047;
            if (n >= 16) {
                int m = n - 16;
                s += gCwv * (gs[b * 2048 + m * 128 + (l >> 4)] * gcw[l & 15] + gcb[l & 15]);
            }
            g_bc[(size_t)tok * 32 + n] = s;
        }
    }
    __syncthreads();

    // ---- delta GEMM: f32x2 over r-pairs, w cached in regs ----
    ull w2r[16];
    const ull* wrow = (const ull*)&dw[tid][0];
#pragma unroll
    for (int k = 0; k < 16; k++) w2r[k] = wrow[k];
    const float bz = bias[d];

    float sd = 0.f;
#pragma unroll 4
    for (int t = 0; t < 32; t++) {
        const ulonglong2* xrow = (const ulonglong2*)&xd[t][0];   // broadcast
        ull a2 = 0ull, b2 = 0ull;
#pragma unroll
        for (int k = 0; k < 8; k++) {
            ulonglong2 qv = xrow[k];
            a2 = fma2(w2r[2 * k],     qv.x, a2);
            b2 = fma2(w2r[2 * k + 1], qv.y, b2);
        }
        float lo, hi; unpackf2(lo, hi, add2(a2, b2));
        float dv = softplusf(lo + hi + bz);
        sd += dv;
        sDl[t][tid] = dv;                               // own column
        g_delta[(size_t)(tokbase + t) * D_IN + tid + dg * 128] = dv;
    }

    // ---- phase-1 chunk scan (same math as old k2) ----
    float cn[16];
#pragma unroll
    for (int n = 0; n < 16; n++)
        cn[n] = -__expf(alogs[(size_t)d * 16 + n]) * LOG2E;
    bool fast = true;
#pragma unroll
    for (int n = 1; n < 16; n++) {
        float want = (float)(n + 1) * cn[0];
        fast = fast && (fabsf(cn[n] - want) <= 1e-4f * fabsf(want));
    }

    const size_t base = (size_t)(b * 1024 + d) * NCHUNK + ch;
    if (fast) {
        const float c0 = cn[0];
        ull h2[8];
#pragma unroll
        for (int k = 0; k < 8; k++) h2[k] = 0ull;
#pragma unroll 4
        for (int s = 0; s < CLEN; s++) {
            float dv = sDl[s][tid];
            float xv = sX[s][tid];
            float e  = ex2f(dv * c0);
            float e2 = e * e;
            float u  = dv * xv;
            ull uu = packf2(u, u);
            ull dd = packf2(e2, e2);
            ull P0 = packf2(e, e2);
            ull D4 = mul2(dd, dd);
            ull P1 = mul2(P0, dd);
            ull D8 = mul2(D4, D4);
            ull P2 = mul2(P0, D4);
            ull P3 = mul2(P1, D4);
            ull P4 = mul2(P0, D8);
            ull P5 = mul2(P1, D8);
            ull P6 = mul2(P2, D8);
            ull P7 = mul2(P3, D8);
            const ulonglong2* B2 = (const ulonglong2*)&sB[s][0];
            ulonglong2 b0 = B2[0], b1 = B2[1], b2v = B2[2], b3 = B2[3];
            h2[0] = fma2(P0, h2[0], mul2(uu, b0.x));
            h2[1] = fma2(P1, h2[1], mul2(uu, b0.y));
            h2[2] = fma2(P2, h2[2], mul2(uu, b1.x));
            h2[3] = fma2(P3, h2[3], mul2(uu, b1.y));
            h2[4] = fma2(P4, h2[4], mul2(uu, b2v.x));
            h2[5] = fma2(P5, h2[5], mul2(uu, b2v.y));
            h2[6] = fma2(P6, h2[6], mul2(uu, b3.x));
            h2[7] = fma2(P7, h2[7], mul2(uu, b3.y));
        }
        g_sd[base] = sd;
#pragma unroll
        for (int k = 0; k < 8; k++) *(ull*)&g_hloc[base * 16 + 2 * k] = h2[k];
    } else {
        float h[16];
#pragma unroll
        for (int n = 0; n < 16; n++) h[n] = 0.f;
        for (int s = 0; s < CLEN; s++) {
            float dv = sDl[s][tid];
            float xv = sX[s][tid];
            float u = dv * xv;
#pragma unroll
            for (int n = 0; n < 16; n++) {
                float a = ex2f(dv * cn[n]);
                h[n] = a * h[n] + u * sB[s][n];
            }
        }
        g_sd[base] = sd;
#pragma unroll
        for (int n = 0; n < 16; n++) g_hloc[base * 16 + n] = h[n];
    }
}

// ------------- K3: hierarchical combine (seg fold / scan / replay) ----------
__global__ __launch_bounds__(128) void k3_combine(const float* __restrict__ alogs)
{
    __shared__ float ssd  [NSEG];
    __shared__ float sHseg[NSEG][16];
    __shared__ float sCar [NSEG][16];

    const int tid = threadIdx.x;
    const int n = tid & 15;
    const int seg = tid >> 4;
    const int bd = blockIdx.x;                 // b*1024 + d
    const int d = bd & 1023;
    const float cnf = -__expf(alogs[(size_t)d * 16 + n]) * LOG2E;
    const size_t base = (size_t)bd * NCHUNK + seg * SEGLEN;

    float sd[SEGLEN], hl[SEGLEN];
#pragma unroll
    for (int j = 0; j < SEGLEN; j++) {
        sd[j] = g_sd[base + j];
        hl[j] = g_hloc[(base + j) * 16 + n];
    }
    float H = 0.f, S = 0.f;
#pragma unroll
    for (int j = 0; j < SEGLEN; j++) {
        H = ex2f(sd[j] * cnf) * H + hl[j];
        S += sd[j];
    }
    sHseg[seg][n] = H;
    if (n == 0) ssd[seg] = S;
    __syncthreads();

    if (tid < 16) {
        float Hc = 0.f;
#pragma unroll
        for (int s = 0; s < NSEG; s++) {
            sCar[s][tid] = Hc;
            Hc = ex2f(ssd[s] * cnf) * Hc + sHseg[s][tid];
        }
    }
    __syncthreads();

    H = sCar[seg][n];
#pragma unroll
    for (int j = 0; j < SEGLEN; j++) {
        g_hin[(base + j) * 16 + n] = H;
        H = ex2f(sd[j] * cnf) * H + hl[j];
    }
}

// ----------------------- K4: scan phase 3 (emit y) --------------------------
__global__ __launch_bounds__(128) void k4_phase3(
    const float* __restrict__ x, const float* __restrict__ alogs,
    const float* __restrict__ Ds, float* __restrict__ y)
{
    __shared__ __align__(16) float sB[CLEN][16];
    __shared__ __align__(16) float sC[CLEN][16];
    __shared__ float sD[CLEN][128];
    __shared__ float sX[CLEN][128];
    const int tid = threadIdx.x;
    const int bid = blockIdx.x;
    const int ch = bid & (NCHUNK - 1);
    const int dg = (bid >> 6) & 7;
    const int b  = bid >> 9;
    const int d  = dg * 128 + tid;
    const int l0 = ch * CLEN;

#pragma unroll
    for (int i = 0; i < 2; i++) {
        int idx = tid + i * 128;
        int s = idx >> 3, qd = idx & 7;
        float4 v = *(const float4*)&g_bc[(size_t)(b * 2048 + l0 + s) * 32 + qd * 4];
        if (qd < 4) ((float4*)&sB[s][0])[qd] = v;
        else        ((float4*)&sC[s][0])[qd - 4] = v;
    }
    __syncthreads();     // protects sB/sC only; before the prefetch

    const size_t base = (size_t)(b * 1024 + d) * NCHUNK + ch;
    ull h2[8];
#pragma unroll
    for (int k = 0; k < 8; k++) h2[k] = *(const ull*)&g_hin[base * 16 + 2 * k];

    const float* dlt = &g_delta[(size_t)(b * 2048 + l0) * D_IN + d];
    const float* xp  = &x[(size_t)(b * 2048 + l0) * D_IN + d];
#pragma unroll
    for (int s = 0; s < CLEN; s++) {
        sD[s][tid] = dlt[(size_t)s * D_IN];
        sX[s][tid] = xp[(size_t)s * D_IN];
    }

    float cn[16];
#pragma unroll
    for (int n = 0; n < 16; n++)
        cn[n] = -__expf(alogs[(size_t)d * 16 + n]) * LOG2E;
    bool fast = true;
#pragma unroll
    for (int n = 1; n < 16; n++) {
        float want = (float)(n + 1) * cn[0];
        fast = fast && (fabsf(cn[n] - want) <= 1e-4f * fabsf(want));
    }

    const float dsv = Ds[d];
    float* yp = &y[(size_t)(b * 2048 + l0) * D_IN + d];

    if (fast) {
        const float c0 = cn[0];
#pragma unroll 4
        for (int s = 0; s < CLEN; s++) {
            float dv = sD[s][tid];
            float xv = sX[s][tid];
            float e  = ex2f(dv * c0);
            float e2 = e * e;
            float u  = dv * xv;
            ull uu = packf2(u, u);
            ull dd = packf2(e2, e2);
            ull P0 = packf2(e, e2);
            ull D4 = mul2(dd, dd);
            ull P1 = mul2(P0, dd);
            ull D8 = mul2(D4, D4);
            ull P2 = mul2(P0, D4);
            ull P3 = mul2(P1, D4);
            ull P4 = mul2(P0, D8);
            ull P5 = mul2(P1, D8);
            ull P6 = mul2(P2, D8);
            ull P7 = mul2(P3, D8);
            const ulonglong2* B2 = (const ulonglong2*)&sB[s][0];
            const ulonglong2* C2 = (const ulonglong2*)&sC[s][0];
            ulonglong2 b0 = B2[0], b1 = B2[1], b2v = B2[2], b3 = B2[3];
            ulonglong2 cc0 = C2[0], cc1 = C2[1], cc2 = C2[2], cc3 = C2[3];
            ull y2a, y2b;
            h2[0] = fma2(P0, h2[0], mul2(uu, b0.x));  y2a = mul2(h2[0], cc0.x);
            h2[1] = fma2(P1, h2[1], mul2(uu, b0.y));  y2b = mul2(h2[1], cc0.y);
            h2[2] = fma2(P2, h2[2], mul2(uu, b1.x));  y2a = fma2(h2[2], cc1.x, y2a);
            h2[3] = fma2(P3, h2[3], mul2(uu, b1.y));  y2b = fma2(h2[3], cc1.y, y2b);
            h2[4] = fma2(P4, h2[4], mul2(uu, b2v.x)); y2a = fma2(h2[4], cc2.x, y2a);
            h2[5] = fma2(P5, h2[5], mul2(uu, b2v.y)); y2b = fma2(h2[5], cc2.y, y2b);
            h2[6] = fma2(P6, h2[6], mul2(uu, b3.x));  y2a = fma2(h2[6], cc3.x, y2a);
            h2[7] = fma2(P7, h2[7], mul2(uu, b3.y));  y2b = fma2(h2[7], cc3.y, y2b);
            float ylo, yhi; unpackf2(ylo, yhi, add2(y2a, y2b));
            yp[(size_t)s * D_IN] = ylo + yhi + xv * dsv;
        }
    } else {
        float h[16];
#pragma unroll
        for (int n = 0; n < 16; n++) { float lo, hi; unpackf2(lo, hi, h2[n >> 1]); h[n] = (n & 1) ? hi : lo; }
        for (int s = 0; s < CLEN; s++) {
            float dv = sD[s][tid];
            float xv = sX[s][tid];
            float u = dv * xv;
            float y0 = 0.f, y1 = 0.f;
#pragma unroll
            for (int n = 0; n < 16; n++) {
                float a = ex2f(dv * cn[n]);
                h[n] = a * h[n] + u * sB[s][n];
                if (n & 1) y1 += h[n] * sC[s][n];
                else       y0 += h[n] * sC[s][n];
            }
            yp[(size_t)s * D_IN] = y0 + y1 + xv * dsv;
        }
    }
}

// ------------------------------- launcher ----------------------------------
extern "C" void kernel_launch(void* const* d_in, const int* in_sizes, int n_in,
                              void* d_out, int out_size)
{
    const float* x     = (const float*)d_in[0];
    const float* gs    = (const float*)d_in[1];
    const float* w1    = (const float*)d_in[2];
    const float* dtw   = (const float*)d_in[3];
    const float* bias  = (const float*)d_in[4];
    const float* alogs = (const float*)d_in[5];
    const float* Ds    = (const float*)d_in[6];
    const float* gcw   = (const float*)d_in[7];
    const float* gcb   = (const float*)d_in[8];
    const float* gCw   = (const float*)d_in[9];
    float* y = (float*)d_out;

    k1a_gemm <<<64 * KSPLIT, 128>>>(x, w1);
    k1b_fused<<<128 * 8, 128>>>(x, dtw, bias, gs, gcw, gcb, gCw, alogs);
    k3_combine<<<BATCH * D_IN, 128>>>(alogs);
    k4_phase3<<<BATCH * 8 * NCHUNK, 128>>>(x, alogs, Ds, y);
}